// round 1
// baseline (speedup 1.0000x reference)
#include <cuda_runtime.h>
#include <math.h>

#define DEV_INLINE __device__ __forceinline__

constexpr int B_  = 8;
constexpr int N_  = 2048;
constexpr int D_  = 384;
constexpr int H_  = 6;
constexpr int DK_ = 64;
constexpr int BN_ = B_ * N_;       // 16384
constexpr int E3_ = 3 * D_;        // 1152
constexpr int FF_ = 2 * D_;        // 768
constexpr int CH_ = 3 + D_;        // 387

// ---------------- scratch (device globals; no allocation allowed) ----------
__device__ float g_feats[BN_ * D_];
__device__ float g_h[BN_ * D_];     // LN1 output, later reused for LN2 output
__device__ float g_q[BN_ * D_];     // (b,h,n,dk)
__device__ float g_k[BN_ * D_];
__device__ float g_v[BN_ * D_];
__device__ float g_ctx[BN_ * D_];   // (b,n,d)
__device__ float g_x[BN_ * D_];     // residual after attention
__device__ float g_ff[BN_ * FF_];

// ---------------- fast exp2 (FMA pipe, avoids MUFU EX2 throughput wall) ----
DEV_INLINE float fexp2(float x) {
    x = fmaxf(x, -125.0f);
    float r = rintf(x);
    float f = x - r;                     // f in [-0.5, 0.5]
    float p = 1.535336188319500e-4f;
    p = fmaf(p, f, 1.339887440266574e-3f);
    p = fmaf(p, f, 9.618437357674640e-3f);
    p = fmaf(p, f, 5.550332471162809e-2f);
    p = fmaf(p, f, 2.402264791363012e-1f);
    p = fmaf(p, f, 6.931472028550421e-1f);
    p = fmaf(p, f, 1.0f);
    int ei = (int)r;
    return __int_as_float((ei + 127) << 23) * p;
}

// ---------------- kernel 1: transpose + LN1 + coords copy ------------------
// grid: 512 blocks (64 per batch, 32 n-rows each), 256 threads
__global__ void k_pre_ln(const float* __restrict__ pts,
                         const float* __restrict__ g1,
                         const float* __restrict__ b1,
                         float* __restrict__ out) {
    __shared__ float S[32][D_];            // 48 KB
    int b  = blockIdx.x >> 6;
    int n0 = (blockIdx.x & 63) << 5;
    const float* base = pts + (size_t)b * CH_ * N_;
    int tid = threadIdx.x;

    // transposed load: coalesced over n
    for (int idx = tid; idx < 32 * D_; idx += 256) {
        int nl = idx & 31, d = idx >> 5;
        S[nl][d] = base[(size_t)(3 + d) * N_ + n0 + nl];
    }
    // coords passthrough
    for (int idx = tid; idx < 96; idx += 256) {
        int nl = idx & 31, c = idx >> 5;
        out[(size_t)b * CH_ * N_ + (size_t)c * N_ + n0 + nl] = base[(size_t)c * N_ + n0 + nl];
    }
    __syncthreads();

    int w = tid >> 5, lane = tid & 31;
    #pragma unroll
    for (int i = 0; i < 4; i++) {
        int nl = w * 4 + i;
        float v[12];
        float s = 0.f, ss = 0.f;
        #pragma unroll
        for (int j = 0; j < 12; j++) {
            v[j] = S[nl][lane + j * 32];
            s += v[j]; ss = fmaf(v[j], v[j], ss);
        }
        #pragma unroll
        for (int o = 16; o; o >>= 1) {
            s  += __shfl_xor_sync(0xffffffffu, s,  o);
            ss += __shfl_xor_sync(0xffffffffu, ss, o);
        }
        float mu   = s * (1.0f / D_);
        float var  = ss * (1.0f / D_) - mu * mu;
        float rstd = rsqrtf(var + 1e-5f);
        size_t row = ((size_t)b * N_ + n0 + nl) * D_;
        #pragma unroll
        for (int j = 0; j < 12; j++) {
            int d = lane + j * 32;
            g_feats[row + d] = v[j];
            g_h[row + d]     = (v[j] - mu) * rstd * g1[d] + b1[d];
        }
    }
}

// ---------------- generic tiled GEMM: C[m,e] = sum_k A[m,k] * W[e,k] -------
// 64x64 tile, BK=32, 256 threads, 4x4 per thread.
// EPI 0: A=g_h,   scatter q/k/v          (KD=384, E=1152)
// EPI 1: A=g_ctx, +b_o +g_feats -> g_x   (KD=384, E=384)
// EPI 2: A=g_h,   +b1, gelu   -> g_ff    (KD=384, E=768)
// EPI 3: A=g_ff,  +b2 +g_x    -> out^T   (KD=768, E=384)
template <int KD, int EPI>
__global__ void k_gemm(const float* __restrict__ W,
                       const float* __restrict__ bias,
                       float* __restrict__ out) {
    __shared__ float As[32][64];
    __shared__ float Bs[32][64];
    const float* A = (EPI == 3) ? g_ff : (EPI == 1 ? g_ctx : g_h);

    int m0 = blockIdx.y * 64;
    int e0 = blockIdx.x * 64;
    int tid = threadIdx.x;
    int tx = tid & 15, ty = tid >> 4;
    float c[4][4] = {};

    for (int k0 = 0; k0 < KD; k0 += 32) {
        #pragma unroll
        for (int i = 0; i < 2; i++) {
            int idx = tid + i * 256;
            int row = idx >> 3;
            int kq  = (idx & 7) * 4;
            float4 t = *(const float4*)&A[(size_t)(m0 + row) * KD + k0 + kq];
            As[kq + 0][row] = t.x; As[kq + 1][row] = t.y;
            As[kq + 2][row] = t.z; As[kq + 3][row] = t.w;
            float4 u = *(const float4*)&W[(size_t)(e0 + row) * KD + k0 + kq];
            Bs[kq + 0][row] = u.x; Bs[kq + 1][row] = u.y;
            Bs[kq + 2][row] = u.z; Bs[kq + 3][row] = u.w;
        }
        __syncthreads();
        #pragma unroll
        for (int k = 0; k < 32; k++) {
            float4 a  = *(const float4*)&As[k][ty * 4];
            float4 bv = *(const float4*)&Bs[k][tx * 4];
            float av[4] = {a.x, a.y, a.z, a.w};
            float bb[4] = {bv.x, bv.y, bv.z, bv.w};
            #pragma unroll
            for (int i = 0; i < 4; i++)
                #pragma unroll
                for (int j = 0; j < 4; j++)
                    c[i][j] = fmaf(av[i], bb[j], c[i][j]);
        }
        __syncthreads();
    }

    int m_base = m0 + ty * 4;
    int e_base = e0 + tx * 4;
    #pragma unroll
    for (int i = 0; i < 4; i++) {
        int m = m_base + i;
        int bb = m >> 11;          // m / 2048
        int n  = m & 2047;
        #pragma unroll
        for (int j = 0; j < 4; j++) {
            int e = e_base + j;
            float val = c[i][j];
            if (EPI == 0) {
                int which = e / D_;
                int el = e - which * D_;
                int h  = el >> 6, dk = el & 63;
                float* dst = (which == 0) ? g_q : (which == 1) ? g_k : g_v;
                dst[(((size_t)bb * H_ + h) * N_ + n) * DK_ + dk] = val;
            } else if (EPI == 1) {
                size_t idx = (size_t)m * D_ + e;
                g_x[idx] = val + bias[e] + g_feats[idx];
            } else if (EPI == 2) {
                float t = val + bias[e];
                g_ff[(size_t)m * FF_ + e] = 0.5f * t * (1.0f + erff(t * 0.70710678118f));
            } else { // EPI == 3
                float t = val + bias[e] + g_x[(size_t)m * D_ + e];
                out[(size_t)bb * CH_ * N_ + (size_t)(3 + e) * N_ + n] = t;
            }
        }
    }
}

// ---------------- kernel 3: flash attention (fp32 SIMT) --------------------
// grid: (N/128, B*H), 128 threads; 1 thread = 1 query row.
__global__ __launch_bounds__(128) void k_attn() {
    __shared__ float Ks[64][64];
    __shared__ float Vs[64][64];
    int bh = blockIdx.y;
    int n  = blockIdx.x * 128 + threadIdx.x;
    const float* qp = g_q + ((size_t)bh * N_ + n) * DK_;
    const float* kp = g_k + (size_t)bh * N_ * DK_;
    const float* vp = g_v + (size_t)bh * N_ * DK_;

    const float sc = 0.125f * 1.44269504f;   // dk^-0.5 * log2(e)
    float q[64];
    #pragma unroll
    for (int d = 0; d < 64; d += 4) {
        float4 t = *(const float4*)&qp[d];
        q[d] = t.x * sc; q[d+1] = t.y * sc; q[d+2] = t.z * sc; q[d+3] = t.w * sc;
    }
    float o[64];
    #pragma unroll
    for (int d = 0; d < 64; d++) o[d] = 0.f;
    float mrun = -1e30f, l = 0.f;

    for (int kt = 0; kt < N_; kt += 64) {
        #pragma unroll
        for (int i = 0; i < 8; i++) {
            int idx = (threadIdx.x + i * 128) * 4;
            int r = idx >> 6, dc = idx & 63;
            *(float4*)&Ks[r][dc] = *(const float4*)&kp[(size_t)(kt + r) * 64 + dc];
            *(float4*)&Vs[r][dc] = *(const float4*)&vp[(size_t)(kt + r) * 64 + dc];
        }
        __syncthreads();

        #pragma unroll
        for (int jc = 0; jc < 64; jc += 16) {
            float s[16];
            #pragma unroll
            for (int j = 0; j < 16; j++) {
                float acc = 0.f;
                #pragma unroll
                for (int d = 0; d < 64; d += 4) {
                    float4 kv = *(const float4*)&Ks[jc + j][d];
                    acc = fmaf(q[d], kv.x, acc);
                    acc = fmaf(q[d+1], kv.y, acc);
                    acc = fmaf(q[d+2], kv.z, acc);
                    acc = fmaf(q[d+3], kv.w, acc);
                }
                s[j] = acc;
            }
            float mc = s[0];
            #pragma unroll
            for (int j = 1; j < 16; j++) mc = fmaxf(mc, s[j]);
            float mn = fmaxf(mrun, mc);
            float resc = fexp2(mrun - mn);
            l *= resc;
            #pragma unroll
            for (int d = 0; d < 64; d++) o[d] *= resc;
            #pragma unroll
            for (int j = 0; j < 16; j++) {
                float p = fexp2(s[j] - mn);
                l += p;
                #pragma unroll
                for (int d = 0; d < 64; d += 4) {
                    float4 vv = *(const float4*)&Vs[jc + j][d];
                    o[d]   = fmaf(p, vv.x, o[d]);
                    o[d+1] = fmaf(p, vv.y, o[d+1]);
                    o[d+2] = fmaf(p, vv.z, o[d+2]);
                    o[d+3] = fmaf(p, vv.w, o[d+3]);
                }
            }
            mrun = mn;
        }
        __syncthreads();
    }

    float inv = 1.0f / l;
    int bb = bh / H_, h = bh - bb * H_;
    float* op = g_ctx + ((size_t)bb * N_ + n) * D_ + h * DK_;
    #pragma unroll
    for (int d = 0; d < 64; d += 4) {
        float4 t;
        t.x = o[d] * inv; t.y = o[d+1] * inv; t.z = o[d+2] * inv; t.w = o[d+3] * inv;
        *(float4*)&op[d] = t;
    }
}

// ---------------- kernel 5: LN2 (rows already contiguous) ------------------
// grid: 2048 blocks, 256 threads, 1 warp = 1 row
__global__ void k_ln2(const float* __restrict__ g2, const float* __restrict__ b2) {
    int row  = blockIdx.x * 8 + (threadIdx.x >> 5);
    int lane = threadIdx.x & 31;
    const float* xr = g_x + (size_t)row * D_;
    float v[12];
    float s = 0.f, ss = 0.f;
    #pragma unroll
    for (int j = 0; j < 12; j++) {
        v[j] = xr[lane + j * 32];
        s += v[j]; ss = fmaf(v[j], v[j], ss);
    }
    #pragma unroll
    for (int o = 16; o; o >>= 1) {
        s  += __shfl_xor_sync(0xffffffffu, s,  o);
        ss += __shfl_xor_sync(0xffffffffu, ss, o);
    }
    float mu   = s * (1.0f / D_);
    float var  = ss * (1.0f / D_) - mu * mu;
    float rstd = rsqrtf(var + 1e-5f);
    float* hr = g_h + (size_t)row * D_;
    #pragma unroll
    for (int j = 0; j < 12; j++) {
        int d = lane + j * 32;
        hr[d] = (v[j] - mu) * rstd * g2[d] + b2[d];
    }
}

// ---------------- launch ---------------------------------------------------
extern "C" void kernel_launch(void* const* d_in, const int* in_sizes, int n_in,
                              void* d_out, int out_size) {
    const float* pts   = (const float*)d_in[0];
    const float* ln1_g = (const float*)d_in[1];
    const float* ln1_b = (const float*)d_in[2];
    const float* w_qkv = (const float*)d_in[3];
    const float* w_o   = (const float*)d_in[4];
    const float* b_o   = (const float*)d_in[5];
    const float* ln2_g = (const float*)d_in[6];
    const float* ln2_b = (const float*)d_in[7];
    const float* w1    = (const float*)d_in[8];
    const float* b1    = (const float*)d_in[9];
    const float* w2    = (const float*)d_in[10];
    const float* b2    = (const float*)d_in[11];
    float* out = (float*)d_out;

    // 1. transpose + LN1 + coords
    k_pre_ln<<<512, 256>>>(pts, ln1_g, ln1_b, out);

    // 2. QKV projection
    k_gemm<D_, 0><<<dim3(E3_ / 64, BN_ / 64), 256>>>(w_qkv, nullptr, nullptr);

    // 3. attention
    k_attn<<<dim3(N_ / 128, B_ * H_), 128>>>();

    // 4. output projection + residual
    k_gemm<D_, 1><<<dim3(D_ / 64, BN_ / 64), 256>>>(w_o, b_o, nullptr);

    // 5. LN2
    k_ln2<<<BN_ / 8, 256>>>(ln2_g, ln2_b);

    // 6. FF1 + GELU
    k_gemm<D_, 2><<<dim3(FF_ / 64, BN_ / 64), 256>>>(w1, b1, nullptr);

    // 7. FF2 + residual + transposed output write
    k_gemm<FF_, 3><<<dim3(D_ / 64, BN_ / 64), 256>>>(w2, b2, out);
}

// round 4
// speedup vs baseline: 3.0731x; 3.0731x over previous
#include <cuda_runtime.h>
#include <math.h>
#include <cstdint>

#define DEV_INLINE __device__ __forceinline__

constexpr int B_  = 8;
constexpr int N_  = 2048;
constexpr int D_  = 384;
constexpr int H_  = 6;
constexpr int DK_ = 64;
constexpr int BN_ = B_ * N_;       // 16384
constexpr int E3_ = 3 * D_;        // 1152
constexpr int FF_ = 2 * D_;        // 768
constexpr int CH_ = 3 + D_;        // 387

// ---------------- scratch (device globals) ----------------------------------
__device__ float g_feats[BN_ * D_];
__device__ float g_h[BN_ * D_];
__device__ float g_qkv[(size_t)BN_ * E3_];                // [token][1152] (V part unused)
__device__ float g_vt[(size_t)B_ * H_ * DK_ * N_];        // [b*H+h][dk][n]  (V transposed)
__device__ float g_ctx[BN_ * D_];
__device__ float g_x[BN_ * D_];
__device__ float g_ff[(size_t)BN_ * FF_];

// ---------------- PTX helpers (sm_80-level only: target-safe) ---------------
DEV_INLINE uint32_t smem_u32(const void* p) {
    uint32_t a;
    asm("{ .reg .u64 t; cvta.to.shared.u64 t, %1; cvt.u32.u64 %0, t; }" : "=r"(a) : "l"(p));
    return a;
}
DEV_INLINE void ldsm4(uint32_t* r, uint32_t addr) {
    asm volatile("ldmatrix.sync.aligned.m8n8.x4.shared.b16 {%0,%1,%2,%3}, [%4];"
        : "=r"(r[0]), "=r"(r[1]), "=r"(r[2]), "=r"(r[3]) : "r"(addr));
}
DEV_INLINE void mma8(float* c, const uint32_t* a, uint32_t b0, uint32_t b1) {
    asm volatile("mma.sync.aligned.m16n8k8.row.col.f32.tf32.tf32.f32 "
        "{%0,%1,%2,%3}, {%4,%5,%6,%7}, {%8,%9}, {%0,%1,%2,%3};"
        : "+f"(c[0]), "+f"(c[1]), "+f"(c[2]), "+f"(c[3])
        : "r"(a[0]), "r"(a[1]), "r"(a[2]), "r"(a[3]), "r"(b0), "r"(b1));
}
DEV_INLINE float to_tf32(float x) {
    uint32_t r;
    asm("cvt.rna.tf32.f32 %0, %1;" : "=r"(r) : "f"(x));
    return __uint_as_float(r);
}

// ---------------- fast exp2 (FMA pipe) --------------------------------------
DEV_INLINE float fexp2(float x) {
    x = fmaxf(x, -125.0f);
    float r = rintf(x);
    float f = x - r;
    float p = 1.535336188319500e-4f;
    p = fmaf(p, f, 1.339887440266574e-3f);
    p = fmaf(p, f, 9.618437357674640e-3f);
    p = fmaf(p, f, 5.550332471162809e-2f);
    p = fmaf(p, f, 2.402264791363012e-1f);
    p = fmaf(p, f, 6.931472028550421e-1f);
    p = fmaf(p, f, 1.0f);
    return __int_as_float(((int)r + 127) << 23) * p;
}

// ---------------- kernel 1: transpose + LN1 + coords ------------------------
__global__ void k_pre_ln(const float* __restrict__ pts,
                         const float* __restrict__ g1,
                         const float* __restrict__ b1,
                         float* __restrict__ out) {
    __shared__ float S[32][D_];
    int b  = blockIdx.x >> 6;
    int n0 = (blockIdx.x & 63) << 5;
    const float* base = pts + (size_t)b * CH_ * N_;
    int tid = threadIdx.x;

    for (int idx = tid; idx < 32 * D_; idx += 256) {
        int nl = idx & 31, d = idx >> 5;
        S[nl][d] = base[(size_t)(3 + d) * N_ + n0 + nl];
    }
    for (int idx = tid; idx < 96; idx += 256) {
        int nl = idx & 31, c = idx >> 5;
        out[(size_t)b * CH_ * N_ + (size_t)c * N_ + n0 + nl] = base[(size_t)c * N_ + n0 + nl];
    }
    __syncthreads();

    int w = tid >> 5, lane = tid & 31;
    #pragma unroll
    for (int i = 0; i < 4; i++) {
        int nl = w * 4 + i;
        float v[12];
        float s = 0.f, ss = 0.f;
        #pragma unroll
        for (int j = 0; j < 12; j++) {
            v[j] = S[nl][lane + j * 32];
            s += v[j]; ss = fmaf(v[j], v[j], ss);
        }
        #pragma unroll
        for (int o = 16; o; o >>= 1) {
            s  += __shfl_xor_sync(0xffffffffu, s,  o);
            ss += __shfl_xor_sync(0xffffffffu, ss, o);
        }
        float mu   = s * (1.0f / D_);
        float var  = ss * (1.0f / D_) - mu * mu;
        float rstd = rsqrtf(var + 1e-5f);
        size_t row = ((size_t)b * N_ + n0 + nl) * D_;
        #pragma unroll
        for (int j = 0; j < 12; j++) {
            int d = lane + j * 32;
            g_feats[row + d] = v[j];
            g_h[row + d]     = (v[j] - mu) * rstd * g1[d] + b1[d];
        }
    }
}

// ---------------- mma.sync tf32 GEMM (3xTF32) -------------------------------
// C[m,e] = sum_k A[m,k] * W[e,k]; tile 128x128, BK=32, 256 thr (8 warps m32n64)
// EPI 0: A=g_h,   -> g_qkv (Q,K) + g_vt (V transposed)   (KD=384, E=1152)
// EPI 1: A=g_ctx, +b_o +g_feats -> g_x                   (KD=384, E=384)
// EPI 2: A=g_h,   +b1, gelu     -> g_ff                  (KD=384, E=768)
// EPI 3: A=g_ff,  +b2 +g_x      -> out^T                 (KD=768, E=384)
constexpr int GS = 36;                       // smem row stride (floats): bank-step 4
constexpr int GEMM_SMEM = 4 * 128 * GS * 4;  // Ah, Al, Bh, Bl = 73728 B

template <int KD, int EPI>
__global__ __launch_bounds__(256) void k_gemm_mma(const float* __restrict__ W,
                                                  const float* __restrict__ bias,
                                                  float* __restrict__ out) {
    extern __shared__ float sm[];
    float* Ah = sm;
    float* Al = sm + 128 * GS;
    float* Bh = sm + 2 * 128 * GS;
    float* Bl = sm + 3 * 128 * GS;
    const uint32_t ah_u = smem_u32(Ah), al_u = smem_u32(Al);
    const uint32_t bh_u = smem_u32(Bh), bl_u = smem_u32(Bl);

    const float* A = (EPI == 3) ? g_ff : (EPI == 1 ? g_ctx : g_h);
    int m0 = blockIdx.y * 128;
    int e0 = blockIdx.x * 128;
    int tid = threadIdx.x;
    int wid = tid >> 5, l = tid & 31;
    int mq = wid & 3, nh = wid >> 2;
    int lr = l & 15, lc = (l >> 4) * 4;      // ldmatrix per-lane row / col-offset

    float c[2][8][4];
    #pragma unroll
    for (int i = 0; i < 2; i++)
        #pragma unroll
        for (int j = 0; j < 8; j++)
            #pragma unroll
            for (int k = 0; k < 4; k++) c[i][j][k] = 0.f;

    for (int kt = 0; kt < KD / 32; kt++) {
        int k0 = kt * 32;
        float4 ra[4], rb[4];
        #pragma unroll
        for (int i = 0; i < 4; i++) {
            int idx = tid + i * 256;
            int row = idx >> 3, c4 = (idx & 7) << 2;
            ra[i] = *(const float4*)&A[(size_t)(m0 + row) * KD + k0 + c4];
            rb[i] = *(const float4*)&W[(size_t)(e0 + row) * KD + k0 + c4];
        }
        __syncthreads();
        #pragma unroll
        for (int i = 0; i < 4; i++) {
            int idx = tid + i * 256;
            int row = idx >> 3, c4 = (idx & 7) << 2;
            int off = row * GS + c4;
            float4 h, lo;
            h.x = to_tf32(ra[i].x); lo.x = to_tf32(ra[i].x - h.x);
            h.y = to_tf32(ra[i].y); lo.y = to_tf32(ra[i].y - h.y);
            h.z = to_tf32(ra[i].z); lo.z = to_tf32(ra[i].z - h.z);
            h.w = to_tf32(ra[i].w); lo.w = to_tf32(ra[i].w - h.w);
            *(float4*)&Ah[off] = h;  *(float4*)&Al[off] = lo;
            h.x = to_tf32(rb[i].x); lo.x = to_tf32(rb[i].x - h.x);
            h.y = to_tf32(rb[i].y); lo.y = to_tf32(rb[i].y - h.y);
            h.z = to_tf32(rb[i].z); lo.z = to_tf32(rb[i].z - h.z);
            h.w = to_tf32(rb[i].w); lo.w = to_tf32(rb[i].w - h.w);
            *(float4*)&Bh[off] = h;  *(float4*)&Bl[off] = lo;
        }
        __syncthreads();

        #pragma unroll
        for (int kc = 0; kc < 4; kc++) {
            uint32_t aoff = (uint32_t)(((mq * 32 + lr) * GS + kc * 8 + lc) * 4);
            uint32_t fah[2][4], fal[2][4];
            ldsm4(fah[0], ah_u + aoff);
            ldsm4(fah[1], ah_u + aoff + 16 * GS * 4);
            ldsm4(fal[0], al_u + aoff);
            ldsm4(fal[1], al_u + aoff + 16 * GS * 4);
            uint32_t boff = (uint32_t)(((nh * 64 + lr) * GS + kc * 8 + lc) * 4);
            uint32_t fbh[4][4], fbl[4][4];
            #pragma unroll
            for (int n4 = 0; n4 < 4; n4++) {
                ldsm4(fbh[n4], bh_u + boff + n4 * 16 * GS * 4);
                ldsm4(fbl[n4], bl_u + boff + n4 * 16 * GS * 4);
            }
            #pragma unroll
            for (int mt = 0; mt < 2; mt++)
                #pragma unroll
                for (int nt = 0; nt < 8; nt++) {
                    uint32_t bh0 = fbh[nt >> 1][nt & 1], bh1 = fbh[nt >> 1][(nt & 1) + 2];
                    uint32_t bl0 = fbl[nt >> 1][nt & 1], bl1 = fbl[nt >> 1][(nt & 1) + 2];
                    mma8(c[mt][nt], fah[mt], bh0, bh1);
                    mma8(c[mt][nt], fal[mt], bh0, bh1);
                    mma8(c[mt][nt], fah[mt], bl0, bl1);
                }
        }
    }

    // epilogue: thread owns rows r0, r0+8; cols cq, cq+1 per n-tile
    int r0 = l >> 2, cq = (l & 3) * 2;
    #pragma unroll
    for (int mt = 0; mt < 2; mt++) {
        #pragma unroll
        for (int mi = 0; mi < 2; mi++) {
            int m  = m0 + mq * 32 + mt * 16 + r0 + mi * 8;
            int bb = m >> 11;
            int n  = m & 2047;
            #pragma unroll
            for (int nt = 0; nt < 8; nt++) {
                int e = e0 + nh * 64 + nt * 8 + cq;
                float v0 = c[mt][nt][mi * 2 + 0];
                float v1 = c[mt][nt][mi * 2 + 1];
                if (EPI == 0) {
                    if (e < 2 * D_) {
                        float2 t = make_float2(v0, v1);
                        *(float2*)&g_qkv[(size_t)m * E3_ + e] = t;
                    } else {
                        int eh = e - 2 * D_;
                        int h  = eh >> 6, dk = eh & 63;
                        size_t base = ((size_t)(bb * H_ + h) * DK_ + dk) * N_ + n;
                        g_vt[base]      = v0;
                        g_vt[base + N_] = v1;
                    }
                } else if (EPI == 1) {
                    size_t idx = (size_t)m * D_ + e;
                    float2 f = *(const float2*)&g_feats[idx];
                    float2 bv = *(const float2*)&bias[e];
                    float2 t = make_float2(v0 + bv.x + f.x, v1 + bv.y + f.y);
                    *(float2*)&g_x[idx] = t;
                } else if (EPI == 2) {
                    float2 bv = *(const float2*)&bias[e];
                    float t0 = v0 + bv.x, t1 = v1 + bv.y;
                    float2 t;
                    t.x = 0.5f * t0 * (1.0f + erff(t0 * 0.70710678118f));
                    t.y = 0.5f * t1 * (1.0f + erff(t1 * 0.70710678118f));
                    *(float2*)&g_ff[(size_t)m * FF_ + e] = t;
                } else {
                    size_t idx = (size_t)m * D_ + e;
                    float2 xv = *(const float2*)&g_x[idx];
                    float2 bv = *(const float2*)&bias[e];
                    size_t ob = (size_t)bb * CH_ * N_;
                    out[ob + (size_t)(3 + e)     * N_ + n] = v0 + bv.x + xv.x;
                    out[ob + (size_t)(3 + e + 1) * N_ + n] = v1 + bv.y + xv.y;
                }
            }
        }
    }
}

// ---------------- flash attention on mma.sync -------------------------------
// grid (N/64, B*H), 128 thr (4 warps); warp = 16 query rows.
// QK: 3xTF32 (Q frags hi/lo in regs, K hi/lo in smem). PV: 1xTF32, V^T from g_vt.
constexpr int AS = 68;                                    // smem stride: bank-step 4
constexpr int ATT_SMEM = (3 * 64 * AS + 4 * 16 * AS) * 4; // Kh,Kl,Vt,Ps = 69632 B

__global__ __launch_bounds__(128) void k_attn_mma() {
    extern __shared__ float sm[];
    float* Kh = sm;
    float* Kl = sm + 64 * AS;
    float* Vt = sm + 2 * 64 * AS;
    float* Ps = sm + 3 * 64 * AS;
    const uint32_t kh_u = smem_u32(Kh), kl_u = smem_u32(Kl);
    const uint32_t vt_u = smem_u32(Vt), ps_u = smem_u32(Ps);

    int bh = blockIdx.y;
    int b  = bh / H_, h = bh - b * H_;
    int q0 = blockIdx.x * 64;
    int tid = threadIdx.x;
    int wid = tid >> 5, l = tid & 31;
    int lr = l & 15, lc = (l >> 4) * 4;
    int r0 = l >> 2, cq = (l & 3) * 2;

    const float sc = 0.125f * 1.44269504f;

    // ---- stage scaled Q (hi/lo) into Kh/Kl, build register fragments -------
    #pragma unroll
    for (int i = 0; i < 8; i++) {
        int idx = tid + i * 128;
        int row = idx >> 4, c4 = (idx & 15) << 2;
        float4 t = *(const float4*)&g_qkv[(size_t)(b * N_ + q0 + row) * E3_ + h * 64 + c4];
        float4 hi, lo;
        hi.x = to_tf32(t.x * sc); lo.x = to_tf32(t.x * sc - hi.x);
        hi.y = to_tf32(t.y * sc); lo.y = to_tf32(t.y * sc - hi.y);
        hi.z = to_tf32(t.z * sc); lo.z = to_tf32(t.z * sc - hi.z);
        hi.w = to_tf32(t.w * sc); lo.w = to_tf32(t.w * sc - hi.w);
        *(float4*)&Kh[row * AS + c4] = hi;
        *(float4*)&Kl[row * AS + c4] = lo;
    }
    __syncthreads();
    uint32_t qh[8][4], ql[8][4];
    {
        uint32_t qoff = (uint32_t)(((wid * 16 + lr) * AS + lc) * 4);
        #pragma unroll
        for (int kc = 0; kc < 8; kc++) {
            ldsm4(qh[kc], kh_u + qoff + kc * 32);
            ldsm4(ql[kc], kl_u + qoff + kc * 32);
        }
    }
    __syncthreads();

    float o[8][4];
    #pragma unroll
    for (int i = 0; i < 8; i++)
        #pragma unroll
        for (int j = 0; j < 4; j++) o[i][j] = 0.f;
    float m0 = -1e30f, m1 = -1e30f, l0 = 0.f, l1 = 0.f;

    const float* vbase = g_vt + (size_t)(b * H_ + h) * DK_ * N_;

    for (int kt0 = 0; kt0 < N_; kt0 += 64) {
        // ---- load K tile (split hi/lo) + V^T tile ---------------------------
        float4 rk[8], rv[8];
        #pragma unroll
        for (int i = 0; i < 8; i++) {
            int idx = tid + i * 128;
            int row = idx >> 4, c4 = (idx & 15) << 2;
            rk[i] = *(const float4*)&g_qkv[(size_t)(b * N_ + kt0 + row) * E3_ + D_ + h * 64 + c4];
            rv[i] = *(const float4*)&vbase[(size_t)row * N_ + kt0 + c4];
        }
        __syncthreads();   // prior iteration's compute done
        #pragma unroll
        for (int i = 0; i < 8; i++) {
            int idx = tid + i * 128;
            int row = idx >> 4, c4 = (idx & 15) << 2;
            float4 hi, lo;
            hi.x = to_tf32(rk[i].x); lo.x = to_tf32(rk[i].x - hi.x);
            hi.y = to_tf32(rk[i].y); lo.y = to_tf32(rk[i].y - hi.y);
            hi.z = to_tf32(rk[i].z); lo.z = to_tf32(rk[i].z - hi.z);
            hi.w = to_tf32(rk[i].w); lo.w = to_tf32(rk[i].w - hi.w);
            *(float4*)&Kh[row * AS + c4] = hi;
            *(float4*)&Kl[row * AS + c4] = lo;
            float4 vv;
            vv.x = to_tf32(rv[i].x); vv.y = to_tf32(rv[i].y);
            vv.z = to_tf32(rv[i].z); vv.w = to_tf32(rv[i].w);
            *(float4*)&Vt[row * AS + c4] = vv;
        }
        __syncthreads();

        // ---- S = Q K^T (3xTF32) --------------------------------------------
        float s[8][4];
        #pragma unroll
        for (int i = 0; i < 8; i++)
            #pragma unroll
            for (int j = 0; j < 4; j++) s[i][j] = 0.f;
        #pragma unroll
        for (int kc = 0; kc < 8; kc++) {
            uint32_t boff = (uint32_t)((lr * AS + kc * 8 + lc) * 4);
            uint32_t fbh[4][4], fbl[4][4];
            #pragma unroll
            for (int n4 = 0; n4 < 4; n4++) {
                ldsm4(fbh[n4], kh_u + boff + n4 * 16 * AS * 4);
                ldsm4(fbl[n4], kl_u + boff + n4 * 16 * AS * 4);
            }
            #pragma unroll
            for (int nt = 0; nt < 8; nt++) {
                uint32_t bh0 = fbh[nt >> 1][nt & 1], bh1 = fbh[nt >> 1][(nt & 1) + 2];
                uint32_t bl0 = fbl[nt >> 1][nt & 1], bl1 = fbl[nt >> 1][(nt & 1) + 2];
                mma8(s[nt], qh[kc], bh0, bh1);
                mma8(s[nt], ql[kc], bh0, bh1);
                mma8(s[nt], qh[kc], bl0, bl1);
            }
        }

        // ---- online softmax -------------------------------------------------
        float mx0 = -1e30f, mx1 = -1e30f;
        #pragma unroll
        for (int nt = 0; nt < 8; nt++) {
            mx0 = fmaxf(mx0, fmaxf(s[nt][0], s[nt][1]));
            mx1 = fmaxf(mx1, fmaxf(s[nt][2], s[nt][3]));
        }
        mx0 = fmaxf(mx0, __shfl_xor_sync(0xffffffffu, mx0, 1));
        mx0 = fmaxf(mx0, __shfl_xor_sync(0xffffffffu, mx0, 2));
        mx1 = fmaxf(mx1, __shfl_xor_sync(0xffffffffu, mx1, 1));
        mx1 = fmaxf(mx1, __shfl_xor_sync(0xffffffffu, mx1, 2));
        float nm0 = fmaxf(m0, mx0), nm1 = fmaxf(m1, mx1);
        float f0 = fexp2(m0 - nm0), f1 = fexp2(m1 - nm1);
        m0 = nm0; m1 = nm1;
        float sum0 = 0.f, sum1 = 0.f;
        float* psw = Ps + wid * 16 * AS;
        #pragma unroll
        for (int nt = 0; nt < 8; nt++) {
            float p0 = fexp2(s[nt][0] - m0);
            float p1 = fexp2(s[nt][1] - m0);
            float p2 = fexp2(s[nt][2] - m1);
            float p3 = fexp2(s[nt][3] - m1);
            sum0 += p0 + p1; sum1 += p2 + p3;
            int col = nt * 8 + cq;
            *(float2*)&psw[r0 * AS + col]       = make_float2(to_tf32(p0), to_tf32(p1));
            *(float2*)&psw[(r0 + 8) * AS + col] = make_float2(to_tf32(p2), to_tf32(p3));
            o[nt][0] *= f0; o[nt][1] *= f0; o[nt][2] *= f1; o[nt][3] *= f1;
        }
        sum0 += __shfl_xor_sync(0xffffffffu, sum0, 1);
        sum0 += __shfl_xor_sync(0xffffffffu, sum0, 2);
        sum1 += __shfl_xor_sync(0xffffffffu, sum1, 1);
        sum1 += __shfl_xor_sync(0xffffffffu, sum1, 2);
        l0 = l0 * f0 + sum0;
        l1 = l1 * f1 + sum1;
        __syncwarp();

        // ---- O += P V (1xTF32) ----------------------------------------------
        uint32_t ps_base = ps_u + wid * 16 * AS * 4;
        #pragma unroll
        for (int kc = 0; kc < 8; kc++) {
            uint32_t fp[4];
            ldsm4(fp, ps_base + (uint32_t)((lr * AS + kc * 8 + lc) * 4));
            uint32_t voff = (uint32_t)((lr * AS + kc * 8 + lc) * 4);
            uint32_t fv[4][4];
            #pragma unroll
            for (int n4 = 0; n4 < 4; n4++)
                ldsm4(fv[n4], vt_u + voff + n4 * 16 * AS * 4);
            #pragma unroll
            for (int nt = 0; nt < 8; nt++)
                mma8(o[nt], fp, fv[nt >> 1][nt & 1], fv[nt >> 1][(nt & 1) + 2]);
        }
        __syncthreads();
    }

    // ---- finalize ----------------------------------------------------------
    float inv0 = 1.0f / l0, inv1 = 1.0f / l1;
    int qa = q0 + wid * 16 + r0;
    #pragma unroll
    for (int nt = 0; nt < 8; nt++) {
        int d = h * 64 + nt * 8 + cq;
        *(float2*)&g_ctx[(size_t)(b * N_ + qa) * D_ + d] =
            make_float2(o[nt][0] * inv0, o[nt][1] * inv0);
        *(float2*)&g_ctx[(size_t)(b * N_ + qa + 8) * D_ + d] =
            make_float2(o[nt][2] * inv1, o[nt][3] * inv1);
    }
}

// ---------------- LN2 -------------------------------------------------------
__global__ void k_ln2(const float* __restrict__ g2, const float* __restrict__ b2) {
    int row  = blockIdx.x * 8 + (threadIdx.x >> 5);
    int lane = threadIdx.x & 31;
    const float* xr = g_x + (size_t)row * D_;
    float v[12];
    float s = 0.f, ss = 0.f;
    #pragma unroll
    for (int j = 0; j < 12; j++) {
        v[j] = xr[lane + j * 32];
        s += v[j]; ss = fmaf(v[j], v[j], ss);
    }
    #pragma unroll
    for (int o = 16; o; o >>= 1) {
        s  += __shfl_xor_sync(0xffffffffu, s,  o);
        ss += __shfl_xor_sync(0xffffffffu, ss, o);
    }
    float mu   = s * (1.0f / D_);
    float var  = ss * (1.0f / D_) - mu * mu;
    float rstd = rsqrtf(var + 1e-5f);
    float* hr = g_h + (size_t)row * D_;
    #pragma unroll
    for (int j = 0; j < 12; j++) {
        int d = lane + j * 32;
        hr[d] = (v[j] - mu) * rstd * g2[d] + b2[d];
    }
}

// ---------------- launch ----------------------------------------------------
extern "C" void kernel_launch(void* const* d_in, const int* in_sizes, int n_in,
                              void* d_out, int out_size) {
    const float* pts   = (const float*)d_in[0];
    const float* ln1_g = (const float*)d_in[1];
    const float* ln1_b = (const float*)d_in[2];
    const float* w_qkv = (const float*)d_in[3];
    const float* w_o   = (const float*)d_in[4];
    const float* b_o   = (const float*)d_in[5];
    const float* ln2_g = (const float*)d_in[6];
    const float* ln2_b = (const float*)d_in[7];
    const float* w1    = (const float*)d_in[8];
    const float* b1    = (const float*)d_in[9];
    const float* w2    = (const float*)d_in[10];
    const float* b2    = (const float*)d_in[11];
    float* out = (float*)d_out;

    static bool attr_done = false;
    if (!attr_done) {
        cudaFuncSetAttribute(k_gemm_mma<D_, 0>,  cudaFuncAttributeMaxDynamicSharedMemorySize, GEMM_SMEM);
        cudaFuncSetAttribute(k_gemm_mma<D_, 1>,  cudaFuncAttributeMaxDynamicSharedMemorySize, GEMM_SMEM);
        cudaFuncSetAttribute(k_gemm_mma<D_, 2>,  cudaFuncAttributeMaxDynamicSharedMemorySize, GEMM_SMEM);
        cudaFuncSetAttribute(k_gemm_mma<FF_, 3>, cudaFuncAttributeMaxDynamicSharedMemorySize, GEMM_SMEM);
        cudaFuncSetAttribute(k_attn_mma,         cudaFuncAttributeMaxDynamicSharedMemorySize, ATT_SMEM);
        attr_done = true;
    }

    k_pre_ln<<<512, 256>>>(pts, ln1_g, ln1_b, out);
    k_gemm_mma<D_, 0><<<dim3(E3_ / 128, BN_ / 128), 256, GEMM_SMEM>>>(w_qkv, nullptr, nullptr);
    k_attn_mma<<<dim3(N_ / 64, B_ * H_), 128, ATT_SMEM>>>();
    k_gemm_mma<D_, 1><<<dim3(D_ / 128, BN_ / 128), 256, GEMM_SMEM>>>(w_o, b_o, nullptr);
    k_ln2<<<BN_ / 8, 256>>>(ln2_g, ln2_b);
    k_gemm_mma<D_, 2><<<dim3(FF_ / 128, BN_ / 128), 256, GEMM_SMEM>>>(w1, b1, nullptr);
    k_gemm_mma<FF_, 3><<<dim3(D_ / 128, BN_ / 128), 256, GEMM_SMEM>>>(w2, b2, out);
}

// round 5
// speedup vs baseline: 4.0782x; 1.3271x over previous
#include <cuda_runtime.h>
#include <cuda_bf16.h>
#include <math.h>
#include <cstdint>

#define DEV_INLINE __device__ __forceinline__

constexpr int B_  = 8;
constexpr int N_  = 2048;
constexpr int D_  = 384;
constexpr int H_  = 6;
constexpr int DK_ = 64;
constexpr int BN_ = B_ * N_;       // 16384
constexpr int E3_ = 3 * D_;        // 1152
constexpr int FF_ = 2 * D_;        // 768
constexpr int CH_ = 3 + D_;        // 387

// ---------------- scratch (device globals) ----------------------------------
__device__ float g_feats[BN_ * D_];
__device__ float g_h[BN_ * D_];
__device__ float g_qkv[(size_t)BN_ * E3_];                // [token][1152] (V part unused)
__device__ float g_vt[(size_t)B_ * H_ * DK_ * N_];        // [b*H+h][dk][n]  (V transposed)
__device__ float g_ctx[BN_ * D_];
__device__ float g_x[BN_ * D_];
__device__ float g_ff[(size_t)BN_ * FF_];

// ---------------- PTX helpers (sm_80-level only: target-safe) ---------------
DEV_INLINE uint32_t smem_u32(const void* p) {
    uint32_t a;
    asm("{ .reg .u64 t; cvta.to.shared.u64 t, %1; cvt.u32.u64 %0, t; }" : "=r"(a) : "l"(p));
    return a;
}
DEV_INLINE void ldsm4(uint32_t* r, uint32_t addr) {
    asm volatile("ldmatrix.sync.aligned.m8n8.x4.shared.b16 {%0,%1,%2,%3}, [%4];"
        : "=r"(r[0]), "=r"(r[1]), "=r"(r[2]), "=r"(r[3]) : "r"(addr));
}
// m16n8k16 bf16 MMA, fp32 accumulate
DEV_INLINE void mma16(float* c, const uint32_t* a, uint32_t b0, uint32_t b1) {
    asm volatile("mma.sync.aligned.m16n8k16.row.col.f32.bf16.bf16.f32 "
        "{%0,%1,%2,%3}, {%4,%5,%6,%7}, {%8,%9}, {%0,%1,%2,%3};"
        : "+f"(c[0]), "+f"(c[1]), "+f"(c[2]), "+f"(c[3])
        : "r"(a[0]), "r"(a[1]), "r"(a[2]), "r"(a[3]), "r"(b0), "r"(b1));
}
DEV_INLINE float bf_hi(float x) { return __bfloat162float(__float2bfloat16_rn(x)); }
DEV_INLINE uint32_t pack_bf(float a, float b) {
    __nv_bfloat162 t = __floats2bfloat162_rn(a, b);
    return *reinterpret_cast<uint32_t*>(&t);
}

// ---------------- fast exp2 (FMA pipe) --------------------------------------
DEV_INLINE float fexp2(float x) {
    x = fmaxf(x, -125.0f);
    float r = rintf(x);
    float f = x - r;
    float p = 1.535336188319500e-4f;
    p = fmaf(p, f, 1.339887440266574e-3f);
    p = fmaf(p, f, 9.618437357674640e-3f);
    p = fmaf(p, f, 5.550332471162809e-2f);
    p = fmaf(p, f, 2.402264791363012e-1f);
    p = fmaf(p, f, 6.931472028550421e-1f);
    p = fmaf(p, f, 1.0f);
    return __int_as_float(((int)r + 127) << 23) * p;
}

// ---------------- kernel 1: transpose + LN1 + coords ------------------------
__global__ void k_pre_ln(const float* __restrict__ pts,
                         const float* __restrict__ g1,
                         const float* __restrict__ b1,
                         float* __restrict__ out) {
    __shared__ float S[32][D_];
    int b  = blockIdx.x >> 6;
    int n0 = (blockIdx.x & 63) << 5;
    const float* base = pts + (size_t)b * CH_ * N_;
    int tid = threadIdx.x;

    for (int idx = tid; idx < 32 * D_; idx += 256) {
        int nl = idx & 31, d = idx >> 5;
        S[nl][d] = base[(size_t)(3 + d) * N_ + n0 + nl];
    }
    for (int idx = tid; idx < 96; idx += 256) {
        int nl = idx & 31, c = idx >> 5;
        out[(size_t)b * CH_ * N_ + (size_t)c * N_ + n0 + nl] = base[(size_t)c * N_ + n0 + nl];
    }
    __syncthreads();

    int w = tid >> 5, lane = tid & 31;
    #pragma unroll
    for (int i = 0; i < 4; i++) {
        int nl = w * 4 + i;
        float v[12];
        float s = 0.f, ss = 0.f;
        #pragma unroll
        for (int j = 0; j < 12; j++) {
            v[j] = S[nl][lane + j * 32];
            s += v[j]; ss = fmaf(v[j], v[j], ss);
        }
        #pragma unroll
        for (int o = 16; o; o >>= 1) {
            s  += __shfl_xor_sync(0xffffffffu, s,  o);
            ss += __shfl_xor_sync(0xffffffffu, ss, o);
        }
        float mu   = s * (1.0f / D_);
        float var  = ss * (1.0f / D_) - mu * mu;
        float rstd = rsqrtf(var + 1e-5f);
        size_t row = ((size_t)b * N_ + n0 + nl) * D_;
        #pragma unroll
        for (int j = 0; j < 12; j++) {
            int d = lane + j * 32;
            g_feats[row + d] = v[j];
            g_h[row + d]     = (v[j] - mu) * rstd * g1[d] + b1[d];
        }
    }
}

// ---------------- mma.sync bf16x3 GEMM --------------------------------------
// C[m,e] = sum_k A[m,k] * W[e,k]; tile 128x128, BK=32, 256 thr (8 warps m32n64)
// smem tiles: bf16x2 packed u32, row = 16 u32 (32 k), XOR chunk swizzle.
constexpr int GEMM_SMEM = 4 * 128 * 16 * 4;   // Ah, Al, Bh, Bl = 32768 B

template <int KD, int EPI>
__global__ __launch_bounds__(256) void k_gemm_mma(const float* __restrict__ W,
                                                  const float* __restrict__ bias,
                                                  float* __restrict__ out) {
    extern __shared__ uint32_t smu[];
    uint32_t* Ah = smu;
    uint32_t* Al = smu + 2048;
    uint32_t* Bh = smu + 4096;
    uint32_t* Bl = smu + 6144;
    const uint32_t ah_u = smem_u32(Ah), al_u = smem_u32(Al);
    const uint32_t bh_u = smem_u32(Bh), bl_u = smem_u32(Bl);

    const float* A = (EPI == 3) ? g_ff : (EPI == 1 ? g_ctx : g_h);
    int m0 = blockIdx.y * 128;
    int e0 = blockIdx.x * 128;
    int tid = threadIdx.x;
    int wid = tid >> 5, l = tid & 31;
    int mq = wid & 3, nh = wid >> 2;
    int lr8 = l & 7, mat = l >> 3;

    float c[2][8][4];
    #pragma unroll
    for (int i = 0; i < 2; i++)
        #pragma unroll
        for (int j = 0; j < 8; j++)
            #pragma unroll
            for (int k = 0; k < 4; k++) c[i][j][k] = 0.f;

    for (int kt = 0; kt < KD / 32; kt++) {
        int k0 = kt * 32;
        float4 ra[4], rb[4];
        #pragma unroll
        for (int i = 0; i < 4; i++) {
            int idx = tid + i * 256;
            int row = idx >> 3, c4 = (idx & 7) << 2;
            ra[i] = *(const float4*)&A[(size_t)(m0 + row) * KD + k0 + c4];
            rb[i] = *(const float4*)&W[(size_t)(e0 + row) * KD + k0 + c4];
        }
        __syncthreads();
        #pragma unroll
        for (int i = 0; i < 4; i++) {
            int idx = tid + i * 256;
            int row = idx >> 3, c4 = (idx & 7) << 2;
            int col = c4 >> 1;                                   // u32 col, in {0,2,..,14}
            int u = row * 16 + (((col >> 2) ^ ((row >> 1) & 3)) << 2) + (col & 3);
            float h0 = bf_hi(ra[i].x), h1 = bf_hi(ra[i].y);
            float h2 = bf_hi(ra[i].z), h3 = bf_hi(ra[i].w);
            uint2 hv = make_uint2(pack_bf(h0, h1), pack_bf(h2, h3));
            uint2 lv = make_uint2(pack_bf(ra[i].x - h0, ra[i].y - h1),
                                  pack_bf(ra[i].z - h2, ra[i].w - h3));
            *(uint2*)&Ah[u] = hv;  *(uint2*)&Al[u] = lv;
            h0 = bf_hi(rb[i].x); h1 = bf_hi(rb[i].y);
            h2 = bf_hi(rb[i].z); h3 = bf_hi(rb[i].w);
            hv = make_uint2(pack_bf(h0, h1), pack_bf(h2, h3));
            lv = make_uint2(pack_bf(rb[i].x - h0, rb[i].y - h1),
                            pack_bf(rb[i].z - h2, rb[i].w - h3));
            *(uint2*)&Bh[u] = hv;  *(uint2*)&Bl[u] = lv;
        }
        __syncthreads();

        #pragma unroll
        for (int kc = 0; kc < 2; kc++) {
            uint32_t fah[2][4], fal[2][4];
            #pragma unroll
            for (int mt = 0; mt < 2; mt++) {
                int r = mq * 32 + mt * 16 + ((mat & 1) << 3) + lr8;
                int cch = kc * 2 + (mat >> 1);
                uint32_t off = (uint32_t)((r * 16 + ((cch ^ ((r >> 1) & 3)) << 2)) * 4);
                ldsm4(fah[mt], ah_u + off);
                ldsm4(fal[mt], al_u + off);
            }
            uint32_t fbh[4][4], fbl[4][4];
            #pragma unroll
            for (int g = 0; g < 4; g++) {
                int r = nh * 64 + g * 16 + ((mat >> 1) << 3) + lr8;
                int cch = kc * 2 + (mat & 1);
                uint32_t off = (uint32_t)((r * 16 + ((cch ^ ((r >> 1) & 3)) << 2)) * 4);
                ldsm4(fbh[g], bh_u + off);
                ldsm4(fbl[g], bl_u + off);
            }
            #pragma unroll
            for (int mt = 0; mt < 2; mt++)
                #pragma unroll
                for (int nt = 0; nt < 8; nt++) {
                    uint32_t b0h = fbh[nt >> 1][(nt & 1) * 2], b1h = fbh[nt >> 1][(nt & 1) * 2 + 1];
                    uint32_t b0l = fbl[nt >> 1][(nt & 1) * 2], b1l = fbl[nt >> 1][(nt & 1) * 2 + 1];
                    mma16(c[mt][nt], fah[mt], b0h, b1h);
                    mma16(c[mt][nt], fal[mt], b0h, b1h);
                    mma16(c[mt][nt], fah[mt], b0l, b1l);
                }
        }
    }

    // epilogue: thread owns rows r0, r0+8; cols cq, cq+1 per n-tile
    int r0 = l >> 2, cq = (l & 3) * 2;
    #pragma unroll
    for (int mt = 0; mt < 2; mt++) {
        #pragma unroll
        for (int mi = 0; mi < 2; mi++) {
            int m  = m0 + mq * 32 + mt * 16 + r0 + mi * 8;
            int bb = m >> 11;
            int n  = m & 2047;
            #pragma unroll
            for (int nt = 0; nt < 8; nt++) {
                int e = e0 + nh * 64 + nt * 8 + cq;
                float v0 = c[mt][nt][mi * 2 + 0];
                float v1 = c[mt][nt][mi * 2 + 1];
                if (EPI == 0) {
                    if (e < 2 * D_) {
                        *(float2*)&g_qkv[(size_t)m * E3_ + e] = make_float2(v0, v1);
                    } else {
                        int eh = e - 2 * D_;
                        int h  = eh >> 6, dk = eh & 63;
                        size_t base = ((size_t)(bb * H_ + h) * DK_ + dk) * N_ + n;
                        g_vt[base]      = v0;
                        g_vt[base + N_] = v1;
                    }
                } else if (EPI == 1) {
                    size_t idx = (size_t)m * D_ + e;
                    float2 f  = *(const float2*)&g_feats[idx];
                    float2 bv = *(const float2*)&bias[e];
                    *(float2*)&g_x[idx] = make_float2(v0 + bv.x + f.x, v1 + bv.y + f.y);
                } else if (EPI == 2) {
                    float2 bv = *(const float2*)&bias[e];
                    float t0 = v0 + bv.x, t1 = v1 + bv.y;
                    float2 t;
                    t.x = 0.5f * t0 * (1.0f + erff(t0 * 0.70710678118f));
                    t.y = 0.5f * t1 * (1.0f + erff(t1 * 0.70710678118f));
                    *(float2*)&g_ff[(size_t)m * FF_ + e] = t;
                } else {
                    size_t idx = (size_t)m * D_ + e;
                    float2 xv = *(const float2*)&g_x[idx];
                    float2 bv = *(const float2*)&bias[e];
                    size_t ob = (size_t)bb * CH_ * N_;
                    out[ob + (size_t)(3 + e)     * N_ + n] = v0 + bv.x + xv.x;
                    out[ob + (size_t)(3 + e + 1) * N_ + n] = v1 + bv.y + xv.y;
                }
            }
        }
    }
}

// ---------------- flash attention on bf16x3 mma.sync ------------------------
// grid (N/64, B*H), 128 thr (4 warps); warp = 16 query rows.
// QK: 3xBF16 (Q frags hi/lo in regs).  PV: 3xBF16 (P split, V split).
constexpr int ATT_SMEM = 12288 * 4;   // Kh,Kl,Vh,Vl (2048 u32 each) + Psh,Psl (2048 each)

__global__ __launch_bounds__(128) void k_attn_mma() {
    extern __shared__ uint32_t smu[];
    uint32_t* Kh  = smu;
    uint32_t* Kl  = smu + 2048;
    uint32_t* Vh  = smu + 4096;
    uint32_t* Vl  = smu + 6144;
    uint32_t* Psh = smu + 8192;
    uint32_t* Psl = smu + 10240;
    const uint32_t kh_u = smem_u32(Kh), kl_u = smem_u32(Kl);
    const uint32_t vh_u = smem_u32(Vh), vl_u = smem_u32(Vl);
    const uint32_t ph_u = smem_u32(Psh), pl_u = smem_u32(Psl);

    int bh = blockIdx.y;
    int b  = bh / H_, h = bh - b * H_;
    int q0 = blockIdx.x * 64;
    int tid = threadIdx.x;
    int wid = tid >> 5, l = tid & 31;
    int lr8 = l & 7, mat = l >> 3;
    int r0 = l >> 2, cq = (l & 3) * 2;

    const float sc = 0.125f * 1.44269504f;

    // ---- stage scaled Q (hi/lo) into Kh/Kl, build register fragments -------
    #pragma unroll
    for (int i = 0; i < 8; i++) {
        int idx = tid + i * 128;
        int row = idx >> 4, c4 = (idx & 15) << 2;
        float4 t = *(const float4*)&g_qkv[(size_t)(b * N_ + q0 + row) * E3_ + h * 64 + c4];
        t.x *= sc; t.y *= sc; t.z *= sc; t.w *= sc;
        int col = c4 >> 1;
        int u = row * 32 + (((col >> 2) ^ (row & 7)) << 2) + (col & 3);
        float h0 = bf_hi(t.x), h1 = bf_hi(t.y), h2 = bf_hi(t.z), h3 = bf_hi(t.w);
        *(uint2*)&Kh[u] = make_uint2(pack_bf(h0, h1), pack_bf(h2, h3));
        *(uint2*)&Kl[u] = make_uint2(pack_bf(t.x - h0, t.y - h1), pack_bf(t.z - h2, t.w - h3));
    }
    __syncthreads();
    uint32_t qh[4][4], ql[4][4];
    #pragma unroll
    for (int kc = 0; kc < 4; kc++) {
        int r = wid * 16 + ((mat & 1) << 3) + lr8;
        int cch = kc * 2 + (mat >> 1);
        uint32_t off = (uint32_t)((r * 32 + ((cch ^ (r & 7)) << 2)) * 4);
        ldsm4(qh[kc], kh_u + off);
        ldsm4(ql[kc], kl_u + off);
    }
    __syncthreads();

    float o[8][4];
    #pragma unroll
    for (int i = 0; i < 8; i++)
        #pragma unroll
        for (int j = 0; j < 4; j++) o[i][j] = 0.f;
    float m0 = -1e30f, m1 = -1e30f, l0 = 0.f, l1 = 0.f;

    const float* vbase = g_vt + (size_t)(b * H_ + h) * DK_ * N_;

    for (int kt0 = 0; kt0 < N_; kt0 += 64) {
        // ---- load K tile + V^T tile (f32), convert to hi/lo bf16 smem ------
        float4 rk[8], rv[8];
        #pragma unroll
        for (int i = 0; i < 8; i++) {
            int idx = tid + i * 128;
            int row = idx >> 4, c4 = (idx & 15) << 2;
            rk[i] = *(const float4*)&g_qkv[(size_t)(b * N_ + kt0 + row) * E3_ + D_ + h * 64 + c4];
            rv[i] = *(const float4*)&vbase[(size_t)row * N_ + kt0 + c4];
        }
        __syncthreads();   // prior iteration's compute done
        #pragma unroll
        for (int i = 0; i < 8; i++) {
            int idx = tid + i * 128;
            int row = idx >> 4, c4 = (idx & 15) << 2;
            int col = c4 >> 1;
            int u = row * 32 + (((col >> 2) ^ (row & 7)) << 2) + (col & 3);
            float h0 = bf_hi(rk[i].x), h1 = bf_hi(rk[i].y);
            float h2 = bf_hi(rk[i].z), h3 = bf_hi(rk[i].w);
            *(uint2*)&Kh[u] = make_uint2(pack_bf(h0, h1), pack_bf(h2, h3));
            *(uint2*)&Kl[u] = make_uint2(pack_bf(rk[i].x - h0, rk[i].y - h1),
                                         pack_bf(rk[i].z - h2, rk[i].w - h3));
            h0 = bf_hi(rv[i].x); h1 = bf_hi(rv[i].y);
            h2 = bf_hi(rv[i].z); h3 = bf_hi(rv[i].w);
            *(uint2*)&Vh[u] = make_uint2(pack_bf(h0, h1), pack_bf(h2, h3));
            *(uint2*)&Vl[u] = make_uint2(pack_bf(rv[i].x - h0, rv[i].y - h1),
                                         pack_bf(rv[i].z - h2, rv[i].w - h3));
        }
        __syncthreads();

        // ---- S = Q K^T (3xBF16) --------------------------------------------
        float s[8][4];
        #pragma unroll
        for (int i = 0; i < 8; i++)
            #pragma unroll
            for (int j = 0; j < 4; j++) s[i][j] = 0.f;
        #pragma unroll
        for (int kc = 0; kc < 4; kc++) {
            uint32_t fbh[4][4], fbl[4][4];
            #pragma unroll
            for (int g = 0; g < 4; g++) {
                int r = g * 16 + ((mat >> 1) << 3) + lr8;
                int cch = kc * 2 + (mat & 1);
                uint32_t off = (uint32_t)((r * 32 + ((cch ^ (r & 7)) << 2)) * 4);
                ldsm4(fbh[g], kh_u + off);
                ldsm4(fbl[g], kl_u + off);
            }
            #pragma unroll
            for (int nt = 0; nt < 8; nt++) {
                uint32_t b0h = fbh[nt >> 1][(nt & 1) * 2], b1h = fbh[nt >> 1][(nt & 1) * 2 + 1];
                uint32_t b0l = fbl[nt >> 1][(nt & 1) * 2], b1l = fbl[nt >> 1][(nt & 1) * 2 + 1];
                mma16(s[nt], qh[kc], b0h, b1h);
                mma16(s[nt], ql[kc], b0h, b1h);
                mma16(s[nt], qh[kc], b0l, b1l);
            }
        }

        // ---- online softmax + P split store --------------------------------
        float mx0 = -1e30f, mx1 = -1e30f;
        #pragma unroll
        for (int nt = 0; nt < 8; nt++) {
            mx0 = fmaxf(mx0, fmaxf(s[nt][0], s[nt][1]));
            mx1 = fmaxf(mx1, fmaxf(s[nt][2], s[nt][3]));
        }
        mx0 = fmaxf(mx0, __shfl_xor_sync(0xffffffffu, mx0, 1));
        mx0 = fmaxf(mx0, __shfl_xor_sync(0xffffffffu, mx0, 2));
        mx1 = fmaxf(mx1, __shfl_xor_sync(0xffffffffu, mx1, 1));
        mx1 = fmaxf(mx1, __shfl_xor_sync(0xffffffffu, mx1, 2));
        float nm0 = fmaxf(m0, mx0), nm1 = fmaxf(m1, mx1);
        float f0 = fexp2(m0 - nm0), f1 = fexp2(m1 - nm1);
        m0 = nm0; m1 = nm1;
        float sum0 = 0.f, sum1 = 0.f;
        int wbase = wid * 512;
        int u0 = wbase + r0 * 32 + (l & 3);
        int u1 = wbase + (r0 + 8) * 32 + (l & 3);
        #pragma unroll
        for (int nt = 0; nt < 8; nt++) {
            float p0 = fexp2(s[nt][0] - m0);
            float p1 = fexp2(s[nt][1] - m0);
            float p2 = fexp2(s[nt][2] - m1);
            float p3 = fexp2(s[nt][3] - m1);
            sum0 += p0 + p1; sum1 += p2 + p3;
            float h0 = bf_hi(p0), h1 = bf_hi(p1), h2 = bf_hi(p2), h3 = bf_hi(p3);
            int sw0 = (nt ^ (r0 & 7)) << 2;
            Psh[u0 + sw0] = pack_bf(h0, h1);
            Psl[u0 + sw0] = pack_bf(p0 - h0, p1 - h1);
            Psh[u1 + sw0] = pack_bf(h2, h3);
            Psl[u1 + sw0] = pack_bf(p2 - h2, p3 - h3);
            o[nt][0] *= f0; o[nt][1] *= f0; o[nt][2] *= f1; o[nt][3] *= f1;
        }
        sum0 += __shfl_xor_sync(0xffffffffu, sum0, 1);
        sum0 += __shfl_xor_sync(0xffffffffu, sum0, 2);
        sum1 += __shfl_xor_sync(0xffffffffu, sum1, 1);
        sum1 += __shfl_xor_sync(0xffffffffu, sum1, 2);
        l0 = l0 * f0 + sum0;
        l1 = l1 * f1 + sum1;
        __syncwarp();

        // ---- O += P V (3xBF16) ---------------------------------------------
        #pragma unroll
        for (int kc = 0; kc < 4; kc++) {
            int rl = ((mat & 1) << 3) + lr8;
            int cch = kc * 2 + (mat >> 1);
            uint32_t poff = (uint32_t)((wbase + rl * 32 + ((cch ^ (rl & 7)) << 2)) * 4);
            uint32_t fph[4], fpl[4];
            ldsm4(fph, ph_u + poff);
            ldsm4(fpl, pl_u + poff);
            uint32_t fvh[4][4], fvl[4][4];
            #pragma unroll
            for (int g = 0; g < 4; g++) {
                int r = g * 16 + ((mat >> 1) << 3) + lr8;
                int cc2 = kc * 2 + (mat & 1);
                uint32_t off = (uint32_t)((r * 32 + ((cc2 ^ (r & 7)) << 2)) * 4);
                ldsm4(fvh[g], vh_u + off);
                ldsm4(fvl[g], vl_u + off);
            }
            #pragma unroll
            for (int nt = 0; nt < 8; nt++) {
                uint32_t b0h = fvh[nt >> 1][(nt & 1) * 2], b1h = fvh[nt >> 1][(nt & 1) * 2 + 1];
                uint32_t b0l = fvl[nt >> 1][(nt & 1) * 2], b1l = fvl[nt >> 1][(nt & 1) * 2 + 1];
                mma16(o[nt], fph, b0h, b1h);
                mma16(o[nt], fpl, b0h, b1h);
                mma16(o[nt], fph, b0l, b1l);
            }
        }
        __syncthreads();
    }

    // ---- finalize ----------------------------------------------------------
    float inv0 = 1.0f / l0, inv1 = 1.0f / l1;
    int qa = q0 + wid * 16 + r0;
    #pragma unroll
    for (int nt = 0; nt < 8; nt++) {
        int d = h * 64 + nt * 8 + cq;
        *(float2*)&g_ctx[(size_t)(b * N_ + qa) * D_ + d] =
            make_float2(o[nt][0] * inv0, o[nt][1] * inv0);
        *(float2*)&g_ctx[(size_t)(b * N_ + qa + 8) * D_ + d] =
            make_float2(o[nt][2] * inv1, o[nt][3] * inv1);
    }
}

// ---------------- LN2 -------------------------------------------------------
__global__ void k_ln2(const float* __restrict__ g2, const float* __restrict__ b2) {
    int row  = blockIdx.x * 8 + (threadIdx.x >> 5);
    int lane = threadIdx.x & 31;
    const float* xr = g_x + (size_t)row * D_;
    float v[12];
    float s = 0.f, ss = 0.f;
    #pragma unroll
    for (int j = 0; j < 12; j++) {
        v[j] = xr[lane + j * 32];
        s += v[j]; ss = fmaf(v[j], v[j], ss);
    }
    #pragma unroll
    for (int o = 16; o; o >>= 1) {
        s  += __shfl_xor_sync(0xffffffffu, s,  o);
        ss += __shfl_xor_sync(0xffffffffu, ss, o);
    }
    float mu   = s * (1.0f / D_);
    float var  = ss * (1.0f / D_) - mu * mu;
    float rstd = rsqrtf(var + 1e-5f);
    float* hr = g_h + (size_t)row * D_;
    #pragma unroll
    for (int j = 0; j < 12; j++) {
        int d = lane + j * 32;
        hr[d] = (v[j] - mu) * rstd * g2[d] + b2[d];
    }
}

// ---------------- launch ----------------------------------------------------
extern "C" void kernel_launch(void* const* d_in, const int* in_sizes, int n_in,
                              void* d_out, int out_size) {
    const float* pts   = (const float*)d_in[0];
    const float* ln1_g = (const float*)d_in[1];
    const float* ln1_b = (const float*)d_in[2];
    const float* w_qkv = (const float*)d_in[3];
    const float* w_o   = (const float*)d_in[4];
    const float* b_o   = (const float*)d_in[5];
    const float* ln2_g = (const float*)d_in[6];
    const float* ln2_b = (const float*)d_in[7];
    const float* w1    = (const float*)d_in[8];
    const float* b1    = (const float*)d_in[9];
    const float* w2    = (const float*)d_in[10];
    const float* b2    = (const float*)d_in[11];
    float* out = (float*)d_out;

    cudaFuncSetAttribute(k_gemm_mma<D_, 0>,  cudaFuncAttributeMaxDynamicSharedMemorySize, GEMM_SMEM);
    cudaFuncSetAttribute(k_gemm_mma<D_, 1>,  cudaFuncAttributeMaxDynamicSharedMemorySize, GEMM_SMEM);
    cudaFuncSetAttribute(k_gemm_mma<D_, 2>,  cudaFuncAttributeMaxDynamicSharedMemorySize, GEMM_SMEM);
    cudaFuncSetAttribute(k_gemm_mma<FF_, 3>, cudaFuncAttributeMaxDynamicSharedMemorySize, GEMM_SMEM);
    cudaFuncSetAttribute(k_attn_mma,         cudaFuncAttributeMaxDynamicSharedMemorySize, ATT_SMEM);

    k_pre_ln<<<512, 256>>>(pts, ln1_g, ln1_b, out);
    k_gemm_mma<D_, 0><<<dim3(E3_ / 128, BN_ / 128), 256, GEMM_SMEM>>>(w_qkv, nullptr, nullptr);
    k_attn_mma<<<dim3(N_ / 64, B_ * H_), 128, ATT_SMEM>>>();
    k_gemm_mma<D_, 1><<<dim3(D_ / 128, BN_ / 128), 256, GEMM_SMEM>>>(w_o, b_o, nullptr);
    k_ln2<<<BN_ / 8, 256>>>(ln2_g, ln2_b);
    k_gemm_mma<D_, 2><<<dim3(FF_ / 128, BN_ / 128), 256, GEMM_SMEM>>>(w1, b1, nullptr);
    k_gemm_mma<FF_, 3><<<dim3(D_ / 128, BN_ / 128), 256, GEMM_SMEM>>>(w2, b2, out);
}

// round 8
// speedup vs baseline: 4.6020x; 1.1285x over previous
#include <cuda_runtime.h>
#include <cuda_bf16.h>
#include <math.h>
#include <cstdint>

#define DEV_INLINE __device__ __forceinline__

constexpr int B_  = 8;
constexpr int N_  = 2048;
constexpr int D_  = 384;
constexpr int H_  = 6;
constexpr int DK_ = 64;
constexpr int BN_ = B_ * N_;       // 16384
constexpr int E3_ = 3 * D_;        // 1152
constexpr int FF_ = 2 * D_;        // 768
constexpr int CH_ = 3 + D_;        // 387

// ---------------- scratch (device globals) ----------------------------------
__device__ float g_feats[BN_ * D_];
__device__ float g_h[BN_ * D_];
__device__ float g_qkv[(size_t)BN_ * E3_];                // [token][1152] (V part unused)
__device__ float g_vt[(size_t)B_ * H_ * DK_ * N_];        // [b*H+h][dk][n]  (V transposed)
__device__ float g_ctx[BN_ * D_];
__device__ float g_x[BN_ * D_];
__device__ float g_ff[(size_t)BN_ * FF_];

// ---------------- PTX helpers (sm_80-level only: target-safe) ---------------
DEV_INLINE uint32_t smem_u32(const void* p) {
    uint32_t a;
    asm("{ .reg .u64 t; cvta.to.shared.u64 t, %1; cvt.u32.u64 %0, t; }" : "=r"(a) : "l"(p));
    return a;
}
DEV_INLINE void ldsm4(uint32_t* r, uint32_t addr) {
    asm volatile("ldmatrix.sync.aligned.m8n8.x4.shared.b16 {%0,%1,%2,%3}, [%4];"
        : "=r"(r[0]), "=r"(r[1]), "=r"(r[2]), "=r"(r[3]) : "r"(addr));
}
// m16n8k16 bf16 MMA, fp32 accumulate
DEV_INLINE void mma16(float* c, const uint32_t* a, uint32_t b0, uint32_t b1) {
    asm volatile("mma.sync.aligned.m16n8k16.row.col.f32.bf16.bf16.f32 "
        "{%0,%1,%2,%3}, {%4,%5,%6,%7}, {%8,%9}, {%0,%1,%2,%3};"
        : "+f"(c[0]), "+f"(c[1]), "+f"(c[2]), "+f"(c[3])
        : "r"(a[0]), "r"(a[1]), "r"(a[2]), "r"(a[3]), "r"(b0), "r"(b1));
}
DEV_INLINE float bf_hi(float x) { return __bfloat162float(__float2bfloat16_rn(x)); }
DEV_INLINE uint32_t pack_bf(float a, float b) {
    __nv_bfloat162 t = __floats2bfloat162_rn(a, b);
    return *reinterpret_cast<uint32_t*>(&t);
}

// ---------------- fast exp2 (FMA pipe) --------------------------------------
DEV_INLINE float fexp2(float x) {
    x = fmaxf(x, -125.0f);
    float r = rintf(x);
    float f = x - r;
    float p = 1.535336188319500e-4f;
    p = fmaf(p, f, 1.339887440266574e-3f);
    p = fmaf(p, f, 9.618437357674640e-3f);
    p = fmaf(p, f, 5.550332471162809e-2f);
    p = fmaf(p, f, 2.402264791363012e-1f);
    p = fmaf(p, f, 6.931472028550421e-1f);
    p = fmaf(p, f, 1.0f);
    return __int_as_float(((int)r + 127) << 23) * p;
}

// ---------------- kernel 1: transpose + LN1 + coords ------------------------
__global__ void k_pre_ln(const float* __restrict__ pts,
                         const float* __restrict__ g1,
                         const float* __restrict__ b1,
                         float* __restrict__ out) {
    __shared__ float S[32][D_];
    int b  = blockIdx.x >> 6;
    int n0 = (blockIdx.x & 63) << 5;
    const float* base = pts + (size_t)b * CH_ * N_;
    int tid = threadIdx.x;

    for (int idx = tid; idx < 32 * D_; idx += 256) {
        int nl = idx & 31, d = idx >> 5;
        S[nl][d] = base[(size_t)(3 + d) * N_ + n0 + nl];
    }
    for (int idx = tid; idx < 96; idx += 256) {
        int nl = idx & 31, c = idx >> 5;
        out[(size_t)b * CH_ * N_ + (size_t)c * N_ + n0 + nl] = base[(size_t)c * N_ + n0 + nl];
    }
    __syncthreads();

    int w = tid >> 5, lane = tid & 31;
    #pragma unroll
    for (int i = 0; i < 4; i++) {
        int nl = w * 4 + i;
        float v[12];
        float s = 0.f, ss = 0.f;
        #pragma unroll
        for (int j = 0; j < 12; j++) {
            v[j] = S[nl][lane + j * 32];
            s += v[j]; ss = fmaf(v[j], v[j], ss);
        }
        #pragma unroll
        for (int o = 16; o; o >>= 1) {
            s  += __shfl_xor_sync(0xffffffffu, s,  o);
            ss += __shfl_xor_sync(0xffffffffu, ss, o);
        }
        float mu   = s * (1.0f / D_);
        float var  = ss * (1.0f / D_) - mu * mu;
        float rstd = rsqrtf(var + 1e-5f);
        size_t row = ((size_t)b * N_ + n0 + nl) * D_;
        #pragma unroll
        for (int j = 0; j < 12; j++) {
            int d = lane + j * 32;
            g_feats[row + d] = v[j];
            g_h[row + d]     = (v[j] - mu) * rstd * g1[d] + b1[d];
        }
    }
}

// ---------------- mma.sync bf16x3 GEMM, double-buffered + reg prefetch ------
// C[m,e] = sum_k A[m,k] W[e,k]; tile 128x128, BK=32, 256 thr (8 warps m32n64)
// smem: 2 stages x {Ah,Al,Bh,Bl} each 128x16 u32; XOR chunk swizzle.
constexpr int GEMM_SMEM = 2 * 4 * 2048 * 4;   // 65536 B

template <int KD, int EPI>
__global__ __launch_bounds__(256, 2) void k_gemm_mma(const float* __restrict__ W,
                                                     const float* __restrict__ bias,
                                                     float* __restrict__ out) {
    extern __shared__ uint32_t smu[];
    const uint32_t sb = smem_u32(smu);

    const float* A = (EPI == 3) ? g_ff : (EPI == 1 ? g_ctx : g_h);
    int m0 = blockIdx.y * 128;
    int e0 = blockIdx.x * 128;
    int tid = threadIdx.x;
    int wid = tid >> 5, l = tid & 31;
    int mq = wid & 3, nh = wid >> 2;
    int lr8 = l & 7, mat = l >> 3;

    float c[2][8][4];
    #pragma unroll
    for (int i = 0; i < 2; i++)
        #pragma unroll
        for (int j = 0; j < 8; j++)
            #pragma unroll
            for (int k = 0; k < 4; k++) c[i][j][k] = 0.f;

    constexpr int KT = KD / 32;

    // prefetch tile 0 into registers
    float4 ra[4], rb[4];
    #pragma unroll
    for (int i = 0; i < 4; i++) {
        int idx = tid + i * 256;
        int row = idx >> 3, c4 = (idx & 7) << 2;
        ra[i] = *(const float4*)&A[(size_t)(m0 + row) * KD + c4];
        rb[i] = *(const float4*)&W[(size_t)(e0 + row) * KD + c4];
    }

    for (int kt = 0; kt < KT; kt++) {
        // ---- convert + store current tile into stage kt&1 ------------------
        uint32_t* Ah = smu + (kt & 1) * 8192;
        uint32_t* Al = Ah + 2048;
        uint32_t* Bh = Ah + 4096;
        uint32_t* Bl = Ah + 6144;
        #pragma unroll
        for (int i = 0; i < 4; i++) {
            int idx = tid + i * 256;
            int row = idx >> 3, c4 = (idx & 7) << 2;
            int col = c4 >> 1;                                   // u32 col, in {0,2,..,14}
            int u = row * 16 + (((col >> 2) ^ ((row >> 1) & 3)) << 2) + (col & 3);
            float h0 = bf_hi(ra[i].x), h1 = bf_hi(ra[i].y);
            float h2 = bf_hi(ra[i].z), h3 = bf_hi(ra[i].w);
            uint2 hv = make_uint2(pack_bf(h0, h1), pack_bf(h2, h3));
            uint2 lv = make_uint2(pack_bf(ra[i].x - h0, ra[i].y - h1),
                                  pack_bf(ra[i].z - h2, ra[i].w - h3));
            *(uint2*)&Ah[u] = hv;  *(uint2*)&Al[u] = lv;
            h0 = bf_hi(rb[i].x); h1 = bf_hi(rb[i].y);
            h2 = bf_hi(rb[i].z); h3 = bf_hi(rb[i].w);
            hv = make_uint2(pack_bf(h0, h1), pack_bf(h2, h3));
            lv = make_uint2(pack_bf(rb[i].x - h0, rb[i].y - h1),
                            pack_bf(rb[i].z - h2, rb[i].w - h3));
            *(uint2*)&Bh[u] = hv;  *(uint2*)&Bl[u] = lv;
        }
        // ---- prefetch next tile (LDG latency hides behind MMA phase) -------
        if (kt + 1 < KT) {
            int k0 = (kt + 1) * 32;
            #pragma unroll
            for (int i = 0; i < 4; i++) {
                int idx = tid + i * 256;
                int row = idx >> 3, c4 = (idx & 7) << 2;
                ra[i] = *(const float4*)&A[(size_t)(m0 + row) * KD + k0 + c4];
                rb[i] = *(const float4*)&W[(size_t)(e0 + row) * KD + k0 + c4];
            }
        }
        __syncthreads();   // stage kt&1 fully written; also separates buffer reuse

        // ---- ldsm + MMA from stage kt&1 ------------------------------------
        uint32_t stg = sb + (uint32_t)(kt & 1) * 32768u;
        uint32_t ah_u = stg, al_u = stg + 8192, bh_u = stg + 16384, bl_u = stg + 24576;
        #pragma unroll
        for (int kc = 0; kc < 2; kc++) {
            uint32_t fah[2][4], fal[2][4];
            #pragma unroll
            for (int mt = 0; mt < 2; mt++) {
                int r = mq * 32 + mt * 16 + ((mat & 1) << 3) + lr8;
                int cch = kc * 2 + (mat >> 1);
                uint32_t off = (uint32_t)((r * 16 + ((cch ^ ((r >> 1) & 3)) << 2)) * 4);
                ldsm4(fah[mt], ah_u + off);
                ldsm4(fal[mt], al_u + off);
            }
            uint32_t fbh[4][4], fbl[4][4];
            #pragma unroll
            for (int g = 0; g < 4; g++) {
                int r = nh * 64 + g * 16 + ((mat >> 1) << 3) + lr8;
                int cch = kc * 2 + (mat & 1);
                uint32_t off = (uint32_t)((r * 16 + ((cch ^ ((r >> 1) & 3)) << 2)) * 4);
                ldsm4(fbh[g], bh_u + off);
                ldsm4(fbl[g], bl_u + off);
            }
            #pragma unroll
            for (int mt = 0; mt < 2; mt++)
                #pragma unroll
                for (int nt = 0; nt < 8; nt++) {
                    uint32_t b0h = fbh[nt >> 1][(nt & 1) * 2], b1h = fbh[nt >> 1][(nt & 1) * 2 + 1];
                    uint32_t b0l = fbl[nt >> 1][(nt & 1) * 2], b1l = fbl[nt >> 1][(nt & 1) * 2 + 1];
                    mma16(c[mt][nt], fah[mt], b0h, b1h);
                    mma16(c[mt][nt], fal[mt], b0h, b1h);
                    mma16(c[mt][nt], fah[mt], b0l, b1l);
                }
        }
        // no trailing barrier: next iteration writes the OTHER stage; reuse of
        // this stage happens at kt+2, separated by kt+1's barrier.
    }

    // epilogue: thread owns rows r0, r0+8; cols cq, cq+1 per n-tile
    int r0 = l >> 2, cq = (l & 3) * 2;
    #pragma unroll
    for (int mt = 0; mt < 2; mt++) {
        #pragma unroll
        for (int mi = 0; mi < 2; mi++) {
            int m  = m0 + mq * 32 + mt * 16 + r0 + mi * 8;
            int bb = m >> 11;
            int n  = m & 2047;
            #pragma unroll
            for (int nt = 0; nt < 8; nt++) {
                int e = e0 + nh * 64 + nt * 8 + cq;
                float v0 = c[mt][nt][mi * 2 + 0];
                float v1 = c[mt][nt][mi * 2 + 1];
                if (EPI == 0) {
                    if (e < 2 * D_) {
                        *(float2*)&g_qkv[(size_t)m * E3_ + e] = make_float2(v0, v1);
                    } else {
                        int eh = e - 2 * D_;
                        int h  = eh >> 6, dk = eh & 63;
                        size_t base = ((size_t)(bb * H_ + h) * DK_ + dk) * N_ + n;
                        g_vt[base]      = v0;
                        g_vt[base + N_] = v1;
                    }
                } else if (EPI == 1) {
                    size_t idx = (size_t)m * D_ + e;
                    float2 f  = *(const float2*)&g_feats[idx];
                    float2 bv = *(const float2*)&bias[e];
                    *(float2*)&g_x[idx] = make_float2(v0 + bv.x + f.x, v1 + bv.y + f.y);
                } else if (EPI == 2) {
                    float2 bv = *(const float2*)&bias[e];
                    float t0 = v0 + bv.x, t1 = v1 + bv.y;
                    float2 t;
                    t.x = 0.5f * t0 * (1.0f + erff(t0 * 0.70710678118f));
                    t.y = 0.5f * t1 * (1.0f + erff(t1 * 0.70710678118f));
                    *(float2*)&g_ff[(size_t)m * FF_ + e] = t;
                } else {
                    size_t idx = (size_t)m * D_ + e;
                    float2 xv = *(const float2*)&g_x[idx];
                    float2 bv = *(const float2*)&bias[e];
                    size_t ob = (size_t)bb * CH_ * N_;
                    out[ob + (size_t)(3 + e)     * N_ + n] = v0 + bv.x + xv.x;
                    out[ob + (size_t)(3 + e + 1) * N_ + n] = v1 + bv.y + xv.y;
                }
            }
        }
    }
}

// ---------------- flash attention on bf16x3 mma.sync (round-5 proven) -------
// grid (N/64, B*H), 128 thr (4 warps); warp = 16 query rows.
constexpr int ATT_SMEM = 12288 * 4;   // Kh,Kl,Vh,Vl,Psh,Psl (2048 u32 each)

__global__ __launch_bounds__(128) void k_attn_mma() {
    extern __shared__ uint32_t smu[];
    uint32_t* Kh  = smu;
    uint32_t* Kl  = smu + 2048;
    uint32_t* Vh  = smu + 4096;
    uint32_t* Vl  = smu + 6144;
    uint32_t* Psh = smu + 8192;
    uint32_t* Psl = smu + 10240;
    const uint32_t kh_u = smem_u32(Kh), kl_u = smem_u32(Kl);
    const uint32_t vh_u = smem_u32(Vh), vl_u = smem_u32(Vl);
    const uint32_t ph_u = smem_u32(Psh), pl_u = smem_u32(Psl);

    int bh = blockIdx.y;
    int b  = bh / H_, h = bh - b * H_;
    int q0 = blockIdx.x * 64;
    int tid = threadIdx.x;
    int wid = tid >> 5, l = tid & 31;
    int lr8 = l & 7, mat = l >> 3;
    int r0 = l >> 2, cq = (l & 3) * 2;

    const float sc = 0.125f * 1.44269504f;

    // ---- stage scaled Q (hi/lo) into Kh/Kl, build register fragments -------
    #pragma unroll
    for (int i = 0; i < 8; i++) {
        int idx = tid + i * 128;
        int row = idx >> 4, c4 = (idx & 15) << 2;
        float4 t = *(const float4*)&g_qkv[(size_t)(b * N_ + q0 + row) * E3_ + h * 64 + c4];
        t.x *= sc; t.y *= sc; t.z *= sc; t.w *= sc;
        int col = c4 >> 1;
        int u = row * 32 + (((col >> 2) ^ (row & 7)) << 2) + (col & 3);
        float h0 = bf_hi(t.x), h1 = bf_hi(t.y), h2 = bf_hi(t.z), h3 = bf_hi(t.w);
        *(uint2*)&Kh[u] = make_uint2(pack_bf(h0, h1), pack_bf(h2, h3));
        *(uint2*)&Kl[u] = make_uint2(pack_bf(t.x - h0, t.y - h1), pack_bf(t.z - h2, t.w - h3));
    }
    __syncthreads();
    uint32_t qh[4][4], ql[4][4];
    #pragma unroll
    for (int kc = 0; kc < 4; kc++) {
        int r = wid * 16 + ((mat & 1) << 3) + lr8;
        int cch = kc * 2 + (mat >> 1);
        uint32_t off = (uint32_t)((r * 32 + ((cch ^ (r & 7)) << 2)) * 4);
        ldsm4(qh[kc], kh_u + off);
        ldsm4(ql[kc], kl_u + off);
    }
    __syncthreads();

    float o[8][4];
    #pragma unroll
    for (int i = 0; i < 8; i++)
        #pragma unroll
        for (int j = 0; j < 4; j++) o[i][j] = 0.f;
    float m0 = -1e30f, m1 = -1e30f, l0 = 0.f, l1 = 0.f;

    const float* vbase = g_vt + (size_t)(b * H_ + h) * DK_ * N_;

    for (int kt0 = 0; kt0 < N_; kt0 += 64) {
        // ---- load K tile + V^T tile (f32), convert to hi/lo bf16 smem ------
        float4 rk[8], rv[8];
        #pragma unroll
        for (int i = 0; i < 8; i++) {
            int idx = tid + i * 128;
            int row = idx >> 4, c4 = (idx & 15) << 2;
            rk[i] = *(const float4*)&g_qkv[(size_t)(b * N_ + kt0 + row) * E3_ + D_ + h * 64 + c4];
            rv[i] = *(const float4*)&vbase[(size_t)row * N_ + kt0 + c4];
        }
        __syncthreads();   // prior iteration's compute done
        #pragma unroll
        for (int i = 0; i < 8; i++) {
            int idx = tid + i * 128;
            int row = idx >> 4, c4 = (idx & 15) << 2;
            int col = c4 >> 1;
            int u = row * 32 + (((col >> 2) ^ (row & 7)) << 2) + (col & 3);
            float h0 = bf_hi(rk[i].x), h1 = bf_hi(rk[i].y);
            float h2 = bf_hi(rk[i].z), h3 = bf_hi(rk[i].w);
            *(uint2*)&Kh[u] = make_uint2(pack_bf(h0, h1), pack_bf(h2, h3));
            *(uint2*)&Kl[u] = make_uint2(pack_bf(rk[i].x - h0, rk[i].y - h1),
                                         pack_bf(rk[i].z - h2, rk[i].w - h3));
            h0 = bf_hi(rv[i].x); h1 = bf_hi(rv[i].y);
            h2 = bf_hi(rv[i].z); h3 = bf_hi(rv[i].w);
            *(uint2*)&Vh[u] = make_uint2(pack_bf(h0, h1), pack_bf(h2, h3));
            *(uint2*)&Vl[u] = make_uint2(pack_bf(rv[i].x - h0, rv[i].y - h1),
                                         pack_bf(rv[i].z - h2, rv[i].w - h3));
        }
        __syncthreads();

        // ---- S = Q K^T (3xBF16) --------------------------------------------
        float s[8][4];
        #pragma unroll
        for (int i = 0; i < 8; i++)
            #pragma unroll
            for (int j = 0; j < 4; j++) s[i][j] = 0.f;
        #pragma unroll
        for (int kc = 0; kc < 4; kc++) {
            uint32_t fbh[4][4], fbl[4][4];
            #pragma unroll
            for (int g = 0; g < 4; g++) {
                int r = g * 16 + ((mat >> 1) << 3) + lr8;
                int cch = kc * 2 + (mat & 1);
                uint32_t off = (uint32_t)((r * 32 + ((cch ^ (r & 7)) << 2)) * 4);
                ldsm4(fbh[g], kh_u + off);
                ldsm4(fbl[g], kl_u + off);
            }
            #pragma unroll
            for (int nt = 0; nt < 8; nt++) {
                uint32_t b0h = fbh[nt >> 1][(nt & 1) * 2], b1h = fbh[nt >> 1][(nt & 1) * 2 + 1];
                uint32_t b0l = fbl[nt >> 1][(nt & 1) * 2], b1l = fbl[nt >> 1][(nt & 1) * 2 + 1];
                mma16(s[nt], qh[kc], b0h, b1h);
                mma16(s[nt], ql[kc], b0h, b1h);
                mma16(s[nt], qh[kc], b0l, b1l);
            }
        }

        // ---- online softmax + P split store --------------------------------
        float mx0 = -1e30f, mx1 = -1e30f;
        #pragma unroll
        for (int nt = 0; nt < 8; nt++) {
            mx0 = fmaxf(mx0, fmaxf(s[nt][0], s[nt][1]));
            mx1 = fmaxf(mx1, fmaxf(s[nt][2], s[nt][3]));
        }
        mx0 = fmaxf(mx0, __shfl_xor_sync(0xffffffffu, mx0, 1));
        mx0 = fmaxf(mx0, __shfl_xor_sync(0xffffffffu, mx0, 2));
        mx1 = fmaxf(mx1, __shfl_xor_sync(0xffffffffu, mx1, 1));
        mx1 = fmaxf(mx1, __shfl_xor_sync(0xffffffffu, mx1, 2));
        float nm0 = fmaxf(m0, mx0), nm1 = fmaxf(m1, mx1);
        float f0 = fexp2(m0 - nm0), f1 = fexp2(m1 - nm1);
        m0 = nm0; m1 = nm1;
        float sum0 = 0.f, sum1 = 0.f;
        int wbase = wid * 512;
        int u0 = wbase + r0 * 32 + (l & 3);
        int u1 = wbase + (r0 + 8) * 32 + (l & 3);
        #pragma unroll
        for (int nt = 0; nt < 8; nt++) {
            float p0 = fexp2(s[nt][0] - m0);
            float p1 = fexp2(s[nt][1] - m0);
            float p2 = fexp2(s[nt][2] - m1);
            float p3 = fexp2(s[nt][3] - m1);
            sum0 += p0 + p1; sum1 += p2 + p3;
            float h0 = bf_hi(p0), h1 = bf_hi(p1), h2 = bf_hi(p2), h3 = bf_hi(p3);
            int sw0 = (nt ^ (r0 & 7)) << 2;
            Psh[u0 + sw0] = pack_bf(h0, h1);
            Psl[u0 + sw0] = pack_bf(p0 - h0, p1 - h1);
            Psh[u1 + sw0] = pack_bf(h2, h3);
            Psl[u1 + sw0] = pack_bf(p2 - h2, p3 - h3);
            o[nt][0] *= f0; o[nt][1] *= f0; o[nt][2] *= f1; o[nt][3] *= f1;
        }
        sum0 += __shfl_xor_sync(0xffffffffu, sum0, 1);
        sum0 += __shfl_xor_sync(0xffffffffu, sum0, 2);
        sum1 += __shfl_xor_sync(0xffffffffu, sum1, 1);
        sum1 += __shfl_xor_sync(0xffffffffu, sum1, 2);
        l0 = l0 * f0 + sum0;
        l1 = l1 * f1 + sum1;
        __syncwarp();

        // ---- O += P V (3xBF16) ---------------------------------------------
        #pragma unroll
        for (int kc = 0; kc < 4; kc++) {
            int rl = ((mat & 1) << 3) + lr8;
            int cch = kc * 2 + (mat >> 1);
            uint32_t poff = (uint32_t)((wbase + rl * 32 + ((cch ^ (rl & 7)) << 2)) * 4);
            uint32_t fph[4], fpl[4];
            ldsm4(fph, ph_u + poff);
            ldsm4(fpl, pl_u + poff);
            uint32_t fvh[4][4], fvl[4][4];
            #pragma unroll
            for (int g = 0; g < 4; g++) {
                int r = g * 16 + ((mat >> 1) << 3) + lr8;
                int cc2 = kc * 2 + (mat & 1);
                uint32_t off = (uint32_t)((r * 32 + ((cc2 ^ (r & 7)) << 2)) * 4);
                ldsm4(fvh[g], vh_u + off);
                ldsm4(fvl[g], vl_u + off);
            }
            #pragma unroll
            for (int nt = 0; nt < 8; nt++) {
                uint32_t b0h = fvh[nt >> 1][(nt & 1) * 2], b1h = fvh[nt >> 1][(nt & 1) * 2 + 1];
                uint32_t b0l = fvl[nt >> 1][(nt & 1) * 2], b1l = fvl[nt >> 1][(nt & 1) * 2 + 1];
                mma16(o[nt], fph, b0h, b1h);
                mma16(o[nt], fpl, b0h, b1h);
                mma16(o[nt], fph, b0l, b1l);
            }
        }
        __syncthreads();
    }

    // ---- finalize ----------------------------------------------------------
    float inv0 = 1.0f / l0, inv1 = 1.0f / l1;
    int qa = q0 + wid * 16 + r0;
    #pragma unroll
    for (int nt = 0; nt < 8; nt++) {
        int d = h * 64 + nt * 8 + cq;
        *(float2*)&g_ctx[(size_t)(b * N_ + qa) * D_ + d] =
            make_float2(o[nt][0] * inv0, o[nt][1] * inv0);
        *(float2*)&g_ctx[(size_t)(b * N_ + qa + 8) * D_ + d] =
            make_float2(o[nt][2] * inv1, o[nt][3] * inv1);
    }
}

// ---------------- LN2 -------------------------------------------------------
__global__ void k_ln2(const float* __restrict__ g2, const float* __restrict__ b2) {
    int row  = blockIdx.x * 8 + (threadIdx.x >> 5);
    int lane = threadIdx.x & 31;
    const float* xr = g_x + (size_t)row * D_;
    float v[12];
    float s = 0.f, ss = 0.f;
    #pragma unroll
    for (int j = 0; j < 12; j++) {
        v[j] = xr[lane + j * 32];
        s += v[j]; ss = fmaf(v[j], v[j], ss);
    }
    #pragma unroll
    for (int o = 16; o; o >>= 1) {
        s  += __shfl_xor_sync(0xffffffffu, s,  o);
        ss += __shfl_xor_sync(0xffffffffu, ss, o);
    }
    float mu   = s * (1.0f / D_);
    float var  = ss * (1.0f / D_) - mu * mu;
    float rstd = rsqrtf(var + 1e-5f);
    float* hr = g_h + (size_t)row * D_;
    #pragma unroll
    for (int j = 0; j < 12; j++) {
        int d = lane + j * 32;
        hr[d] = (v[j] - mu) * rstd * g2[d] + b2[d];
    }
}

// ---------------- launch ----------------------------------------------------
extern "C" void kernel_launch(void* const* d_in, const int* in_sizes, int n_in,
                              void* d_out, int out_size) {
    const float* pts   = (const float*)d_in[0];
    const float* ln1_g = (const float*)d_in[1];
    const float* ln1_b = (const float*)d_in[2];
    const float* w_qkv = (const float*)d_in[3];
    const float* w_o   = (const float*)d_in[4];
    const float* b_o   = (const float*)d_in[5];
    const float* ln2_g = (const float*)d_in[6];
    const float* ln2_b = (const float*)d_in[7];
    const float* w1    = (const float*)d_in[8];
    const float* b1    = (const float*)d_in[9];
    const float* w2    = (const float*)d_in[10];
    const float* b2    = (const float*)d_in[11];
    float* out = (float*)d_out;

    cudaFuncSetAttribute(k_gemm_mma<D_, 0>,  cudaFuncAttributeMaxDynamicSharedMemorySize, GEMM_SMEM);
    cudaFuncSetAttribute(k_gemm_mma<D_, 1>,  cudaFuncAttributeMaxDynamicSharedMemorySize, GEMM_SMEM);
    cudaFuncSetAttribute(k_gemm_mma<D_, 2>,  cudaFuncAttributeMaxDynamicSharedMemorySize, GEMM_SMEM);
    cudaFuncSetAttribute(k_gemm_mma<FF_, 3>, cudaFuncAttributeMaxDynamicSharedMemorySize, GEMM_SMEM);
    cudaFuncSetAttribute(k_attn_mma,         cudaFuncAttributeMaxDynamicSharedMemorySize, ATT_SMEM);

    k_pre_ln<<<512, 256>>>(pts, ln1_g, ln1_b, out);
    k_gemm_mma<D_, 0><<<dim3(E3_ / 128, BN_ / 128), 256, GEMM_SMEM>>>(w_qkv, nullptr, nullptr);
    k_attn_mma<<<dim3(N_ / 64, B_ * H_), 128, ATT_SMEM>>>();
    k_gemm_mma<D_, 1><<<dim3(D_ / 128, BN_ / 128), 256, GEMM_SMEM>>>(w_o, b_o, nullptr);
    k_ln2<<<BN_ / 8, 256>>>(ln2_g, ln2_b);
    k_gemm_mma<D_, 2><<<dim3(FF_ / 128, BN_ / 128), 256, GEMM_SMEM>>>(w1, b1, nullptr);
    k_gemm_mma<FF_, 3><<<dim3(D_ / 128, BN_ / 128), 256, GEMM_SMEM>>>(w2, b2, out);
}

// round 10
// speedup vs baseline: 4.7581x; 1.0339x over previous
#include <cuda_runtime.h>
#include <cuda_bf16.h>
#include <math.h>
#include <cstdint>

#define DEV_INLINE __device__ __forceinline__

constexpr int B_  = 8;
constexpr int N_  = 2048;
constexpr int D_  = 384;
constexpr int H_  = 6;
constexpr int DK_ = 64;
constexpr int BN_ = B_ * N_;       // 16384
constexpr int E3_ = 3 * D_;        // 1152
constexpr int FF_ = 2 * D_;        // 768
constexpr int CH_ = 3 + D_;        // 387
constexpr int D2_ = D_ / 2;        // 192 u32 per row

// ---------------- scratch (device globals) ----------------------------------
__device__ float    g_feats[BN_ * D_];
__device__ float    g_x[BN_ * D_];
__device__ uint32_t g_hh[BN_ * D2_],   g_hl[BN_ * D2_];       // LN out split
__device__ uint32_t g_qh[BN_ * D2_],   g_ql[BN_ * D2_];       // Q split
__device__ uint32_t g_ksh[BN_ * D2_],  g_ksl[BN_ * D2_];      // K split
__device__ uint16_t g_vth[(size_t)B_ * H_ * DK_ * N_];        // V^T hi bf16 [bh][dk][n]
__device__ uint16_t g_vtl[(size_t)B_ * H_ * DK_ * N_];        // V^T lo bf16
__device__ uint32_t g_ctxh[BN_ * D2_], g_ctxl[BN_ * D2_];     // attn ctx split
__device__ uint32_t g_ffh[BN_ * FF_ / 2], g_ffl[BN_ * FF_ / 2];
__device__ uint32_t g_wqh[E3_ * D2_],  g_wql[E3_ * D2_];
__device__ uint32_t g_woh[D_ * D2_],   g_wol[D_ * D2_];
__device__ uint32_t g_w1h[FF_ * D2_],  g_w1l[FF_ * D2_];
__device__ uint32_t g_w2h[D_ * FF_/2], g_w2l[D_ * FF_/2];

// ---------------- PTX helpers (sm_80-level only: target-safe) ---------------
DEV_INLINE uint32_t smem_u32(const void* p) {
    uint32_t a;
    asm("{ .reg .u64 t; cvta.to.shared.u64 t, %1; cvt.u32.u64 %0, t; }" : "=r"(a) : "l"(p));
    return a;
}
DEV_INLINE void ldsm4(uint32_t* r, uint32_t addr) {
    asm volatile("ldmatrix.sync.aligned.m8n8.x4.shared.b16 {%0,%1,%2,%3}, [%4];"
        : "=r"(r[0]), "=r"(r[1]), "=r"(r[2]), "=r"(r[3]) : "r"(addr));
}
DEV_INLINE void mma16(float* c, const uint32_t* a, uint32_t b0, uint32_t b1) {
    asm volatile("mma.sync.aligned.m16n8k16.row.col.f32.bf16.bf16.f32 "
        "{%0,%1,%2,%3}, {%4,%5,%6,%7}, {%8,%9}, {%0,%1,%2,%3};"
        : "+f"(c[0]), "+f"(c[1]), "+f"(c[2]), "+f"(c[3])
        : "r"(a[0]), "r"(a[1]), "r"(a[2]), "r"(a[3]), "r"(b0), "r"(b1));
}
DEV_INLINE float bf_hi(float x) { return __bfloat162float(__float2bfloat16_rn(x)); }
DEV_INLINE uint32_t pack_bf(float a, float b) {
    __nv_bfloat162 t = __floats2bfloat162_rn(a, b);
    return *reinterpret_cast<uint32_t*>(&t);
}
DEV_INLINE uint16_t bf_bits(float x) {
    __nv_bfloat16 t = __float2bfloat16_rn(x);
    return *reinterpret_cast<uint16_t*>(&t);
}

// ---------------- fast exp2 (FMA pipe) --------------------------------------
DEV_INLINE float fexp2(float x) {
    x = fmaxf(x, -125.0f);
    float r = rintf(x);
    float f = x - r;
    float p = 1.535336188319500e-4f;
    p = fmaf(p, f, 1.339887440266574e-3f);
    p = fmaf(p, f, 9.618437357674640e-3f);
    p = fmaf(p, f, 5.550332471162809e-2f);
    p = fmaf(p, f, 2.402264791363012e-1f);
    p = fmaf(p, f, 6.931472028550421e-1f);
    p = fmaf(p, f, 1.0f);
    return __int_as_float(((int)r + 127) << 23) * p;
}

// ---------------- weight split ----------------------------------------------
// Destination device globals selected IN DEVICE CODE (passing __device__
// symbols as host-side kernel args gives the host shadow address — on GB300
// ATS makes that silently dereferenceable, so the device arrays stay zero).
template <int W>
__global__ void k_split(const float* __restrict__ src, int n2) {
    uint32_t* dh; uint32_t* dl;
    if constexpr (W == 0)      { dh = g_wqh; dl = g_wql; }
    else if constexpr (W == 1) { dh = g_woh; dl = g_wol; }
    else if constexpr (W == 2) { dh = g_w1h; dl = g_w1l; }
    else                       { dh = g_w2h; dl = g_w2l; }
    int i = blockIdx.x * 256 + threadIdx.x;
    if (i < n2) {
        float2 v = *(const float2*)&src[(size_t)i * 2];
        float h0 = bf_hi(v.x), h1 = bf_hi(v.y);
        dh[i] = pack_bf(h0, h1);
        dl[i] = pack_bf(v.x - h0, v.y - h1);
    }
}

// ---------------- kernel 1: transpose + LN1 + coords ------------------------
__global__ void k_pre_ln(const float* __restrict__ pts,
                         const float* __restrict__ g1,
                         const float* __restrict__ b1,
                         float* __restrict__ out) {
    __shared__ float S[32][D_];
    int b  = blockIdx.x >> 6;
    int n0 = (blockIdx.x & 63) << 5;
    const float* base = pts + (size_t)b * CH_ * N_;
    int tid = threadIdx.x;

    for (int idx = tid; idx < 32 * D_; idx += 256) {
        int nl = idx & 31, d = idx >> 5;
        S[nl][d] = base[(size_t)(3 + d) * N_ + n0 + nl];
    }
    for (int idx = tid; idx < 96; idx += 256) {
        int nl = idx & 31, c = idx >> 5;
        out[(size_t)b * CH_ * N_ + (size_t)c * N_ + n0 + nl] = base[(size_t)c * N_ + n0 + nl];
    }
    __syncthreads();

    int w = tid >> 5, lane = tid & 31;
    #pragma unroll
    for (int i = 0; i < 4; i++) {
        int nl = w * 4 + i;
        float va[6], vb[6];
        float s = 0.f, ss = 0.f;
        #pragma unroll
        for (int j = 0; j < 6; j++) {
            int d = (lane + j * 32) * 2;
            va[j] = S[nl][d]; vb[j] = S[nl][d + 1];
            s += va[j] + vb[j];
            ss = fmaf(va[j], va[j], ss); ss = fmaf(vb[j], vb[j], ss);
        }
        #pragma unroll
        for (int o = 16; o; o >>= 1) {
            s  += __shfl_xor_sync(0xffffffffu, s,  o);
            ss += __shfl_xor_sync(0xffffffffu, ss, o);
        }
        float mu   = s * (1.0f / D_);
        float var  = ss * (1.0f / D_) - mu * mu;
        float rstd = rsqrtf(var + 1e-5f);
        size_t row = (size_t)b * N_ + n0 + nl;
        #pragma unroll
        for (int j = 0; j < 6; j++) {
            int d = (lane + j * 32) * 2;
            *(float2*)&g_feats[row * D_ + d] = make_float2(va[j], vb[j]);
            float2 gg = *(const float2*)&g1[d];
            float2 bb = *(const float2*)&b1[d];
            float ha = (va[j] - mu) * rstd * gg.x + bb.x;
            float hb = (vb[j] - mu) * rstd * gg.y + bb.y;
            float h0 = bf_hi(ha), h1 = bf_hi(hb);
            g_hh[row * D2_ + lane + j * 32] = pack_bf(h0, h1);
            g_hl[row * D2_ + lane + j * 32] = pack_bf(ha - h0, hb - h1);
        }
    }
}

// ---------------- bf16x3 GEMM, pre-split operands, double-buffered ----------
// C[m,e] = sum_k A[m,k] W[e,k]; tile 128x128, BK=32, 256 thr (8 warps m32n64)
constexpr int GEMM_SMEM = 2 * 4 * 2048 * 4;   // 65536 B

template <int KD, int EPI>
__global__ __launch_bounds__(256, 2) void k_gemm_mma(const float* __restrict__ bias,
                                                     float* __restrict__ out) {
    extern __shared__ uint32_t smu[];
    const uint32_t sb = smem_u32(smu);
    constexpr int KD2 = KD / 2;

    const uint32_t *Ahg, *Alg, *Bhg, *Blg;
    if constexpr (EPI == 0)      { Ahg = g_hh;   Alg = g_hl;   Bhg = g_wqh; Blg = g_wql; }
    else if constexpr (EPI == 1) { Ahg = g_ctxh; Alg = g_ctxl; Bhg = g_woh; Blg = g_wol; }
    else if constexpr (EPI == 2) { Ahg = g_hh;   Alg = g_hl;   Bhg = g_w1h; Blg = g_w1l; }
    else                         { Ahg = g_ffh;  Alg = g_ffl;  Bhg = g_w2h; Blg = g_w2l; }

    int m0 = blockIdx.y * 128;
    int e0 = blockIdx.x * 128;
    int tid = threadIdx.x;
    int wid = tid >> 5, l = tid & 31;
    int mq = wid & 3, nh = wid >> 2;
    int lr8 = l & 7, mat = l >> 3;

    float c[2][8][4];
    #pragma unroll
    for (int i = 0; i < 2; i++)
        #pragma unroll
        for (int j = 0; j < 8; j++)
            #pragma unroll
            for (int k = 0; k < 4; k++) c[i][j][k] = 0.f;

    constexpr int KT = KD / 32;

    uint2 pah[4], pal[4], pbh[4], pbl[4];
    // prefetch tile 0
    #pragma unroll
    for (int i = 0; i < 4; i++) {
        int idx = tid + i * 256;
        int row = idx >> 3, c2 = (idx & 7) << 1;
        size_t ao = (size_t)(m0 + row) * KD2 + c2;
        size_t bo = (size_t)(e0 + row) * KD2 + c2;
        pah[i] = *(const uint2*)&Ahg[ao];
        pal[i] = *(const uint2*)&Alg[ao];
        pbh[i] = *(const uint2*)&Bhg[bo];
        pbl[i] = *(const uint2*)&Blg[bo];
    }

    for (int kt = 0; kt < KT; kt++) {
        // ---- store current tile into stage kt&1 ----------------------------
        uint32_t* Ah = smu + (kt & 1) * 8192;
        uint32_t* Al = Ah + 2048;
        uint32_t* Bh = Ah + 4096;
        uint32_t* Bl = Ah + 6144;
        #pragma unroll
        for (int i = 0; i < 4; i++) {
            int idx = tid + i * 256;
            int row = idx >> 3, c2 = (idx & 7) << 1;
            int u = row * 16 + (((c2 >> 2) ^ ((row >> 1) & 3)) << 2) + (c2 & 3);
            *(uint2*)&Ah[u] = pah[i];
            *(uint2*)&Al[u] = pal[i];
            *(uint2*)&Bh[u] = pbh[i];
            *(uint2*)&Bl[u] = pbl[i];
        }
        // ---- prefetch next tile (hides LDG behind MMA phase) ---------------
        if (kt + 1 < KT) {
            int k2 = (kt + 1) * 16;
            #pragma unroll
            for (int i = 0; i < 4; i++) {
                int idx = tid + i * 256;
                int row = idx >> 3, c2 = (idx & 7) << 1;
                size_t ao = (size_t)(m0 + row) * KD2 + k2 + c2;
                size_t bo = (size_t)(e0 + row) * KD2 + k2 + c2;
                pah[i] = *(const uint2*)&Ahg[ao];
                pal[i] = *(const uint2*)&Alg[ao];
                pbh[i] = *(const uint2*)&Bhg[bo];
                pbl[i] = *(const uint2*)&Blg[bo];
            }
        }
        __syncthreads();   // stage kt&1 written; separates buffer reuse (kt+2)

        // ---- ldsm + MMA from stage kt&1 ------------------------------------
        uint32_t stg = sb + (uint32_t)(kt & 1) * 32768u;
        uint32_t ah_u = stg, al_u = stg + 8192, bh_u = stg + 16384, bl_u = stg + 24576;
        #pragma unroll
        for (int kc = 0; kc < 2; kc++) {
            uint32_t fah[2][4], fal[2][4];
            #pragma unroll
            for (int mt = 0; mt < 2; mt++) {
                int r = mq * 32 + mt * 16 + ((mat & 1) << 3) + lr8;
                int cch = kc * 2 + (mat >> 1);
                uint32_t off = (uint32_t)((r * 16 + ((cch ^ ((r >> 1) & 3)) << 2)) * 4);
                ldsm4(fah[mt], ah_u + off);
                ldsm4(fal[mt], al_u + off);
            }
            uint32_t fbh[4][4], fbl[4][4];
            #pragma unroll
            for (int g = 0; g < 4; g++) {
                int r = nh * 64 + g * 16 + ((mat >> 1) << 3) + lr8;
                int cch = kc * 2 + (mat & 1);
                uint32_t off = (uint32_t)((r * 16 + ((cch ^ ((r >> 1) & 3)) << 2)) * 4);
                ldsm4(fbh[g], bh_u + off);
                ldsm4(fbl[g], bl_u + off);
            }
            #pragma unroll
            for (int mt = 0; mt < 2; mt++)
                #pragma unroll
                for (int nt = 0; nt < 8; nt++) {
                    uint32_t b0h = fbh[nt >> 1][(nt & 1) * 2], b1h = fbh[nt >> 1][(nt & 1) * 2 + 1];
                    uint32_t b0l = fbl[nt >> 1][(nt & 1) * 2], b1l = fbl[nt >> 1][(nt & 1) * 2 + 1];
                    mma16(c[mt][nt], fah[mt], b0h, b1h);
                    mma16(c[mt][nt], fal[mt], b0h, b1h);
                    mma16(c[mt][nt], fah[mt], b0l, b1l);
                }
        }
    }

    // epilogue
    int r0 = l >> 2, cq = (l & 3) * 2;
    #pragma unroll
    for (int mt = 0; mt < 2; mt++) {
        #pragma unroll
        for (int mi = 0; mi < 2; mi++) {
            int m  = m0 + mq * 32 + mt * 16 + r0 + mi * 8;
            int bb = m >> 11;
            int n  = m & 2047;
            #pragma unroll
            for (int nt = 0; nt < 8; nt++) {
                int e = e0 + nh * 64 + nt * 8 + cq;
                float v0 = c[mt][nt][mi * 2 + 0];
                float v1 = c[mt][nt][mi * 2 + 1];
                if (EPI == 0) {
                    if (e < 2 * D_) {
                        float h0 = bf_hi(v0), h1 = bf_hi(v1);
                        uint32_t ph = pack_bf(h0, h1);
                        uint32_t pl = pack_bf(v0 - h0, v1 - h1);
                        if (e < D_) {
                            g_qh[(size_t)m * D2_ + (e >> 1)] = ph;
                            g_ql[(size_t)m * D2_ + (e >> 1)] = pl;
                        } else {
                            g_ksh[(size_t)m * D2_ + ((e - D_) >> 1)] = ph;
                            g_ksl[(size_t)m * D2_ + ((e - D_) >> 1)] = pl;
                        }
                    } else {
                        int eh = e - 2 * D_;
                        int hh = eh >> 6, dk = eh & 63;
                        size_t base = ((size_t)(bb * H_ + hh) * DK_ + dk) * N_ + n;
                        float h0 = bf_hi(v0);
                        g_vth[base] = bf_bits(v0);
                        g_vtl[base] = bf_bits(v0 - h0);
                        float h1 = bf_hi(v1);
                        g_vth[base + N_] = bf_bits(v1);
                        g_vtl[base + N_] = bf_bits(v1 - h1);
                    }
                } else if (EPI == 1) {
                    size_t idx = (size_t)m * D_ + e;
                    float2 f  = *(const float2*)&g_feats[idx];
                    float2 bv = *(const float2*)&bias[e];
                    *(float2*)&g_x[idx] = make_float2(v0 + bv.x + f.x, v1 + bv.y + f.y);
                } else if (EPI == 2) {
                    float2 bv = *(const float2*)&bias[e];
                    float t0 = v0 + bv.x, t1 = v1 + bv.y;
                    float u0 = 0.5f * t0 * (1.0f + erff(t0 * 0.70710678118f));
                    float u1 = 0.5f * t1 * (1.0f + erff(t1 * 0.70710678118f));
                    float h0 = bf_hi(u0), h1 = bf_hi(u1);
                    g_ffh[(size_t)m * (FF_/2) + (e >> 1)] = pack_bf(h0, h1);
                    g_ffl[(size_t)m * (FF_/2) + (e >> 1)] = pack_bf(u0 - h0, u1 - h1);
                } else {
                    size_t idx = (size_t)m * D_ + e;
                    float2 xv = *(const float2*)&g_x[idx];
                    float2 bv = *(const float2*)&bias[e];
                    size_t ob = (size_t)bb * CH_ * N_;
                    out[ob + (size_t)(3 + e)     * N_ + n] = v0 + bv.x + xv.x;
                    out[ob + (size_t)(3 + e + 1) * N_ + n] = v1 + bv.y + xv.y;
                }
            }
        }
    }
}

// ---------------- flash attention, pre-split operands -----------------------
// grid (N/64, B*H), 128 thr (4 warps); warp = 16 query rows.
constexpr int ATT_SMEM = 12288 * 4;   // Kh,Kl,Vh,Vl,Psh,Psl (2048 u32 each)

__global__ __launch_bounds__(128) void k_attn_mma() {
    extern __shared__ uint32_t smu[];
    uint32_t* Kh  = smu;
    uint32_t* Kl  = smu + 2048;
    uint32_t* Vh  = smu + 4096;
    uint32_t* Vl  = smu + 6144;
    uint32_t* Psh = smu + 8192;
    uint32_t* Psl = smu + 10240;
    const uint32_t kh_u = smem_u32(Kh), kl_u = smem_u32(Kl);
    const uint32_t vh_u = smem_u32(Vh), vl_u = smem_u32(Vl);
    const uint32_t ph_u = smem_u32(Psh), pl_u = smem_u32(Psl);

    int bh = blockIdx.y;
    int b  = bh / H_, h = bh - b * H_;
    int q0 = blockIdx.x * 64;
    int tid = threadIdx.x;
    int wid = tid >> 5, l = tid & 31;
    int lr8 = l & 7, mat = l >> 3;
    int r0 = l >> 2, cq = (l & 3) * 2;

    const float SC = 0.125f * 1.44269504f;
    const size_t vtb = (size_t)(b * H_ + h) * DK_ * N_;

    // ---- stage Q (pre-split) into Kh/Kl, build register fragments ----------
    #pragma unroll
    for (int i = 0; i < 8; i++) {
        int idx = tid + i * 128;
        int row = idx >> 4, c2 = (idx & 15) << 1;
        int u = row * 32 + (((c2 >> 2) ^ (row & 7)) << 2) + (c2 & 3);
        size_t so = (size_t)(b * N_ + q0 + row) * D2_ + h * 32 + c2;
        *(uint2*)&Kh[u] = *(const uint2*)&g_qh[so];
        *(uint2*)&Kl[u] = *(const uint2*)&g_ql[so];
    }
    __syncthreads();
    uint32_t qh[4][4], ql[4][4];
    #pragma unroll
    for (int kc = 0; kc < 4; kc++) {
        int r = wid * 16 + ((mat & 1) << 3) + lr8;
        int cch = kc * 2 + (mat >> 1);
        uint32_t off = (uint32_t)((r * 32 + ((cch ^ (r & 7)) << 2)) * 4);
        ldsm4(qh[kc], kh_u + off);
        ldsm4(ql[kc], kl_u + off);
    }
    __syncthreads();

    float o[8][4];
    #pragma unroll
    for (int i = 0; i < 8; i++)
        #pragma unroll
        for (int j = 0; j < 4; j++) o[i][j] = 0.f;
    float m0 = -1e30f, m1 = -1e30f, l0 = 0.f, l1 = 0.f;

    for (int kt0 = 0; kt0 < N_; kt0 += 64) {
        // ---- load K + V^T tiles (pre-split) --------------------------------
        uint2 rkh[8], rkl[8], rvh[8], rvl[8];
        #pragma unroll
        for (int i = 0; i < 8; i++) {
            int idx = tid + i * 128;
            int row = idx >> 4, c2 = (idx & 15) << 1, c4 = (idx & 15) << 2;
            size_t so = (size_t)(b * N_ + kt0 + row) * D2_ + h * 32 + c2;
            rkh[i] = *(const uint2*)&g_ksh[so];
            rkl[i] = *(const uint2*)&g_ksl[so];
            size_t vo = vtb + (size_t)row * N_ + kt0 + c4;
            rvh[i] = *(const uint2*)&g_vth[vo];
            rvl[i] = *(const uint2*)&g_vtl[vo];
        }
        __syncthreads();   // prior iteration's compute done
        #pragma unroll
        for (int i = 0; i < 8; i++) {
            int idx = tid + i * 128;
            int row = idx >> 4, c2 = (idx & 15) << 1;
            int u = row * 32 + (((c2 >> 2) ^ (row & 7)) << 2) + (c2 & 3);
            *(uint2*)&Kh[u] = rkh[i];
            *(uint2*)&Kl[u] = rkl[i];
            *(uint2*)&Vh[u] = rvh[i];
            *(uint2*)&Vl[u] = rvl[i];
        }
        __syncthreads();

        // ---- S = Q K^T (3xBF16), scale post-MMA ----------------------------
        float s[8][4];
        #pragma unroll
        for (int i = 0; i < 8; i++)
            #pragma unroll
            for (int j = 0; j < 4; j++) s[i][j] = 0.f;
        #pragma unroll
        for (int kc = 0; kc < 4; kc++) {
            uint32_t fbh[4][4], fbl[4][4];
            #pragma unroll
            for (int g = 0; g < 4; g++) {
                int r = g * 16 + ((mat >> 1) << 3) + lr8;
                int cch = kc * 2 + (mat & 1);
                uint32_t off = (uint32_t)((r * 32 + ((cch ^ (r & 7)) << 2)) * 4);
                ldsm4(fbh[g], kh_u + off);
                ldsm4(fbl[g], kl_u + off);
            }
            #pragma unroll
            for (int nt = 0; nt < 8; nt++) {
                uint32_t b0h = fbh[nt >> 1][(nt & 1) * 2], b1h = fbh[nt >> 1][(nt & 1) * 2 + 1];
                uint32_t b0l = fbl[nt >> 1][(nt & 1) * 2], b1l = fbl[nt >> 1][(nt & 1) * 2 + 1];
                mma16(s[nt], qh[kc], b0h, b1h);
                mma16(s[nt], ql[kc], b0h, b1h);
                mma16(s[nt], qh[kc], b0l, b1l);
            }
        }
        #pragma unroll
        for (int nt = 0; nt < 8; nt++) {
            s[nt][0] *= SC; s[nt][1] *= SC; s[nt][2] *= SC; s[nt][3] *= SC;
        }

        // ---- online softmax + P split store --------------------------------
        float mx0 = -1e30f, mx1 = -1e30f;
        #pragma unroll
        for (int nt = 0; nt < 8; nt++) {
            mx0 = fmaxf(mx0, fmaxf(s[nt][0], s[nt][1]));
            mx1 = fmaxf(mx1, fmaxf(s[nt][2], s[nt][3]));
        }
        mx0 = fmaxf(mx0, __shfl_xor_sync(0xffffffffu, mx0, 1));
        mx0 = fmaxf(mx0, __shfl_xor_sync(0xffffffffu, mx0, 2));
        mx1 = fmaxf(mx1, __shfl_xor_sync(0xffffffffu, mx1, 1));
        mx1 = fmaxf(mx1, __shfl_xor_sync(0xffffffffu, mx1, 2));
        float nm0 = fmaxf(m0, mx0), nm1 = fmaxf(m1, mx1);
        float f0 = fexp2(m0 - nm0), f1 = fexp2(m1 - nm1);
        m0 = nm0; m1 = nm1;
        float sum0 = 0.f, sum1 = 0.f;
        int wbase = wid * 512;
        int u0 = wbase + r0 * 32 + (l & 3);
        int u1 = wbase + (r0 + 8) * 32 + (l & 3);
        #pragma unroll
        for (int nt = 0; nt < 8; nt++) {
            float p0 = fexp2(s[nt][0] - m0);
            float p1 = fexp2(s[nt][1] - m0);
            float p2 = fexp2(s[nt][2] - m1);
            float p3 = fexp2(s[nt][3] - m1);
            sum0 += p0 + p1; sum1 += p2 + p3;
            float h0 = bf_hi(p0), h1 = bf_hi(p1), h2 = bf_hi(p2), h3 = bf_hi(p3);
            int sw0 = (nt ^ (r0 & 7)) << 2;
            Psh[u0 + sw0] = pack_bf(h0, h1);
            Psl[u0 + sw0] = pack_bf(p0 - h0, p1 - h1);
            Psh[u1 + sw0] = pack_bf(h2, h3);
            Psl[u1 + sw0] = pack_bf(p2 - h2, p3 - h3);
            o[nt][0] *= f0; o[nt][1] *= f0; o[nt][2] *= f1; o[nt][3] *= f1;
        }
        sum0 += __shfl_xor_sync(0xffffffffu, sum0, 1);
        sum0 += __shfl_xor_sync(0xffffffffu, sum0, 2);
        sum1 += __shfl_xor_sync(0xffffffffu, sum1, 1);
        sum1 += __shfl_xor_sync(0xffffffffu, sum1, 2);
        l0 = l0 * f0 + sum0;
        l1 = l1 * f1 + sum1;
        __syncwarp();

        // ---- O += P V (3xBF16) ---------------------------------------------
        #pragma unroll
        for (int kc = 0; kc < 4; kc++) {
            int rl = ((mat & 1) << 3) + lr8;
            int cch = kc * 2 + (mat >> 1);
            uint32_t poff = (uint32_t)((wbase + rl * 32 + ((cch ^ (rl & 7)) << 2)) * 4);
            uint32_t fph[4], fpl[4];
            ldsm4(fph, ph_u + poff);
            ldsm4(fpl, pl_u + poff);
            uint32_t fvh[4][4], fvl[4][4];
            #pragma unroll
            for (int g = 0; g < 4; g++) {
                int r = g * 16 + ((mat >> 1) << 3) + lr8;
                int cc2 = kc * 2 + (mat & 1);
                uint32_t off = (uint32_t)((r * 32 + ((cc2 ^ (r & 7)) << 2)) * 4);
                ldsm4(fvh[g], vh_u + off);
                ldsm4(fvl[g], vl_u + off);
            }
            #pragma unroll
            for (int nt = 0; nt < 8; nt++) {
                uint32_t b0h = fvh[nt >> 1][(nt & 1) * 2], b1h = fvh[nt >> 1][(nt & 1) * 2 + 1];
                uint32_t b0l = fvl[nt >> 1][(nt & 1) * 2], b1l = fvl[nt >> 1][(nt & 1) * 2 + 1];
                mma16(o[nt], fph, b0h, b1h);
                mma16(o[nt], fpl, b0h, b1h);
                mma16(o[nt], fph, b0l, b1l);
            }
        }
        __syncthreads();
    }

    // ---- finalize: write split ctx -----------------------------------------
    float inv0 = 1.0f / l0, inv1 = 1.0f / l1;
    int qa = q0 + wid * 16 + r0;
    #pragma unroll
    for (int nt = 0; nt < 8; nt++) {
        int d2 = (h * 64 + nt * 8 + cq) >> 1;
        float a0 = o[nt][0] * inv0, a1 = o[nt][1] * inv0;
        float h0 = bf_hi(a0), h1 = bf_hi(a1);
        g_ctxh[(size_t)(b * N_ + qa) * D2_ + d2] = pack_bf(h0, h1);
        g_ctxl[(size_t)(b * N_ + qa) * D2_ + d2] = pack_bf(a0 - h0, a1 - h1);
        float a2 = o[nt][2] * inv1, a3 = o[nt][3] * inv1;
        float h2 = bf_hi(a2), h3 = bf_hi(a3);
        g_ctxh[(size_t)(b * N_ + qa + 8) * D2_ + d2] = pack_bf(h2, h3);
        g_ctxl[(size_t)(b * N_ + qa + 8) * D2_ + d2] = pack_bf(a2 - h2, a3 - h3);
    }
}

// ---------------- LN2: read g_x f32, write split ----------------------------
__global__ void k_ln2(const float* __restrict__ g2, const float* __restrict__ b2) {
    int row  = blockIdx.x * 8 + (threadIdx.x >> 5);
    int lane = threadIdx.x & 31;
    const float* xr = g_x + (size_t)row * D_;
    float va[6], vb[6];
    float s = 0.f, ss = 0.f;
    #pragma unroll
    for (int j = 0; j < 6; j++) {
        float2 t = *(const float2*)&xr[(lane + j * 32) * 2];
        va[j] = t.x; vb[j] = t.y;
        s += t.x + t.y;
        ss = fmaf(t.x, t.x, ss); ss = fmaf(t.y, t.y, ss);
    }
    #pragma unroll
    for (int o = 16; o; o >>= 1) {
        s  += __shfl_xor_sync(0xffffffffu, s,  o);
        ss += __shfl_xor_sync(0xffffffffu, ss, o);
    }
    float mu   = s * (1.0f / D_);
    float var  = ss * (1.0f / D_) - mu * mu;
    float rstd = rsqrtf(var + 1e-5f);
    #pragma unroll
    for (int j = 0; j < 6; j++) {
        int d = (lane + j * 32) * 2;
        float2 gg = *(const float2*)&g2[d];
        float2 bb = *(const float2*)&b2[d];
        float ha = (va[j] - mu) * rstd * gg.x + bb.x;
        float hb = (vb[j] - mu) * rstd * gg.y + bb.y;
        float h0 = bf_hi(ha), h1 = bf_hi(hb);
        g_hh[(size_t)row * D2_ + lane + j * 32] = pack_bf(h0, h1);
        g_hl[(size_t)row * D2_ + lane + j * 32] = pack_bf(ha - h0, hb - h1);
    }
}

// ---------------- launch ----------------------------------------------------
extern "C" void kernel_launch(void* const* d_in, const int* in_sizes, int n_in,
                              void* d_out, int out_size) {
    const float* pts   = (const float*)d_in[0];
    const float* ln1_g = (const float*)d_in[1];
    const float* ln1_b = (const float*)d_in[2];
    const float* w_qkv = (const float*)d_in[3];
    const float* w_o   = (const float*)d_in[4];
    const float* b_o   = (const float*)d_in[5];
    const float* ln2_g = (const float*)d_in[6];
    const float* ln2_b = (const float*)d_in[7];
    const float* w1    = (const float*)d_in[8];
    const float* b1    = (const float*)d_in[9];
    const float* w2    = (const float*)d_in[10];
    const float* b2    = (const float*)d_in[11];
    float* out = (float*)d_out;

    cudaFuncSetAttribute(k_gemm_mma<D_, 0>,  cudaFuncAttributeMaxDynamicSharedMemorySize, GEMM_SMEM);
    cudaFuncSetAttribute(k_gemm_mma<D_, 1>,  cudaFuncAttributeMaxDynamicSharedMemorySize, GEMM_SMEM);
    cudaFuncSetAttribute(k_gemm_mma<D_, 2>,  cudaFuncAttributeMaxDynamicSharedMemorySize, GEMM_SMEM);
    cudaFuncSetAttribute(k_gemm_mma<FF_, 3>, cudaFuncAttributeMaxDynamicSharedMemorySize, GEMM_SMEM);
    cudaFuncSetAttribute(k_attn_mma,         cudaFuncAttributeMaxDynamicSharedMemorySize, ATT_SMEM);

    // weight splits: destinations bound in device code (template tag)
    k_split<0><<<(E3_ * D2_ + 255) / 256, 256>>>(w_qkv, E3_ * D2_);
    k_split<1><<<(D_ * D2_ + 255) / 256, 256>>>(w_o, D_ * D2_);
    k_split<2><<<(FF_ * D2_ + 255) / 256, 256>>>(w1, FF_ * D2_);
    k_split<3><<<(D_ * FF_ / 2 + 255) / 256, 256>>>(w2, D_ * FF_ / 2);

    k_pre_ln<<<512, 256>>>(pts, ln1_g, ln1_b, out);
    k_gemm_mma<D_, 0><<<dim3(E3_ / 128, BN_ / 128), 256, GEMM_SMEM>>>(nullptr, nullptr);
    k_attn_mma<<<dim3(N_ / 64, B_ * H_), 128, ATT_SMEM>>>();
    k_gemm_mma<D_, 1><<<dim3(D_ / 128, BN_ / 128), 256, GEMM_SMEM>>>(b_o, nullptr);
    k_ln2<<<BN_ / 8, 256>>>(ln2_g, ln2_b);
    k_gemm_mma<D_, 2><<<dim3(FF_ / 128, BN_ / 128), 256, GEMM_SMEM>>>(b1, nullptr);
    k_gemm_mma<FF_, 3><<<dim3(D_ / 128, BN_ / 128), 256, GEMM_SMEM>>>(b2, out);
}